// round 5
// baseline (speedup 1.0000x reference)
#include <cuda_runtime.h>

#define NN 100000
#define EE 1600000
#define EP (EE + NN)
#define NEG 0.2f

// ---------------- scratch (static device globals; no allocation) ----------------
__device__ int   g_deg[NN];
__device__ float g_sumattr[NN * 16];
__device__ float g_mean[NN * 16];
__device__ float g_h1[(size_t)NN * 128];
__device__ float g_als1[NN * 4];
__device__ float g_ald1[NN * 4];
__device__ float g_ale1[(size_t)EP * 4];
__device__ float g_p1[(size_t)EP * 4];
__device__ float g_z1[NN * 4];
__device__ float g_agg1[(size_t)NN * 128];
__device__ float g_h1o[(size_t)NN * 128];
__device__ float g_h2l[(size_t)NN * 32];
__device__ float g_als2[NN];
__device__ float g_ald2[NN];
__device__ float g_ale2[EP];
__device__ float g_p2[EP];
__device__ float g_z2[NN];
__device__ float g_agg2[(size_t)NN * 32];

__device__ __forceinline__ float lrelu(float x) { return x > 0.f ? x : NEG * x; }
__device__ __forceinline__ float elu(float x)   { return x > 0.f ? x : expm1f(x); }

// ---------------- init ----------------
__global__ void kz() {
    int i = blockIdx.x * blockDim.x + threadIdx.x;           // over NN*128
    if (i < NN) { g_deg[i] = 0; g_z2[i] = 0.f; }
    if (i < NN * 4)  g_z1[i] = 0.f;
    if (i < NN * 16) g_sumattr[i] = 0.f;
    if (i < NN * 32) g_agg2[i] = 0.f;
    if (i < NN * 128) g_agg1[i] = 0.f;
}

__global__ void k_outzero(float* out, int n) {
    int i = blockIdx.x * blockDim.x + threadIdx.x;
    if (i < n) out[i] = 0.f;
}

// ---------------- degree + edge-attr sums per dst ----------------
__global__ void k_deg(const int* __restrict__ ei, const float* __restrict__ ea) {
    int e = blockIdx.x * blockDim.x + threadIdx.x;
    if (e >= EE) return;
    int d = ei[EE + e];
    atomicAdd(&g_deg[d], 1);
    for (int j = 0; j < 16; j++)
        atomicAdd(&g_sumattr[d * 16 + j], ea[(size_t)e * 16 + j]);
}

__global__ void k_mean() {
    int t = blockIdx.x * blockDim.x + threadIdx.x;           // over NN*16
    if (t >= NN * 16) return;
    int n = t >> 4;
    g_mean[t] = g_sumattr[t] / fmaxf((float)g_deg[n], 1.f);
}

// ---------------- dumb GEMM: h1[n,j] = sum_k x[n,k] W1[k,j]  (128x128) ----------------
__global__ void k_gemm1d(const float* __restrict__ X, const float* __restrict__ W) {
    int t = blockIdx.x * blockDim.x + threadIdx.x;           // over NN*128
    if (t >= NN * 128) return;
    int n = t >> 7, j = t & 127;
    float s = 0.f;
    for (int k = 0; k < 128; k++)
        s += X[(size_t)n * 128 + k] * W[k * 128 + j];
    g_h1[t] = s;
}

// ---------------- layer-1 attention dots ----------------
__global__ void k_att1d(const float* __restrict__ a1s, const float* __restrict__ a1d) {
    int t = blockIdx.x * blockDim.x + threadIdx.x;           // over NN*4
    if (t >= NN * 4) return;
    int n = t >> 2, h = t & 3;
    float s = 0.f, d = 0.f;
    for (int c = 0; c < 32; c++) {
        float v = g_h1[(size_t)n * 128 + h * 32 + c];
        s += v * a1s[h * 32 + c];
        d += v * a1d[h * 32 + c];
    }
    g_als1[t] = s; g_ald1[t] = d;
}

// ---------------- layer-1 edge-feature attention term (explicit he) ----------------
__global__ void k_ale1(const float* __restrict__ ea, const float* __restrict__ W1e,
                       const float* __restrict__ a1e) {
    int t = blockIdx.x * blockDim.x + threadIdx.x;           // over EP*4
    if (t >= EP * 4) return;
    int e = t >> 2, h = t & 3;
    const float* attr = (e < EE) ? (ea + (size_t)e * 16) : (g_mean + (size_t)(e - EE) * 16);
    float al = 0.f;
    for (int c = 0; c < 32; c++) {
        float he = 0.f;
        for (int ed = 0; ed < 16; ed++)
            he += attr[ed] * W1e[ed * 128 + h * 32 + c];
        al += he * a1e[h * 32 + c];
    }
    g_ale1[t] = al;
}

// ---------------- layer-1 softmax numerators + denominators ----------------
__global__ void k_e1(const int* __restrict__ ei) {
    int t = blockIdx.x * blockDim.x + threadIdx.x;           // over EP*4
    if (t >= EP * 4) return;
    int e = t >> 2, h = t & 3;
    int s, d;
    if (e < EE) { s = ei[e]; d = ei[EE + e]; } else { s = e - EE; d = s; }
    float logit = lrelu(g_als1[s * 4 + h] + g_ald1[d * 4 + h] + g_ale1[t]);
    float p = expf(logit);
    g_p1[t] = p;
    atomicAdd(&g_z1[d * 4 + h], p);
}

// ---------------- layer-1 gather (per (edge, channel) atomic) ----------------
__global__ void k_g1(const int* __restrict__ ei) {
    int t = blockIdx.x * blockDim.x + threadIdx.x;           // over EP*128
    if (t >= EP * 128) return;
    int e = t >> 7, j = t & 127, h = j >> 5;
    int s, d;
    if (e < EE) { s = ei[e]; d = ei[EE + e]; } else { s = e - EE; d = s; }
    float alpha = g_p1[(size_t)e * 4 + h] / g_z1[d * 4 + h];
    atomicAdd(&g_agg1[(size_t)d * 128 + j], alpha * g_h1[(size_t)s * 128 + j]);
}

__global__ void k_h1o(const float* __restrict__ b1) {
    int t = blockIdx.x * blockDim.x + threadIdx.x;           // over NN*128
    if (t >= NN * 128) return;
    g_h1o[t] = elu(g_agg1[t] + b1[t & 127]);
}

// ---------------- dumb GEMM2: h2l[n,c] = sum_k h1o[n,k] W2[k,c] ----------------
__global__ void k_gemm2d(const float* __restrict__ W) {
    int t = blockIdx.x * blockDim.x + threadIdx.x;           // over NN*32
    if (t >= NN * 32) return;
    int n = t >> 5, c = t & 31;
    float s = 0.f;
    for (int k = 0; k < 128; k++)
        s += g_h1o[(size_t)n * 128 + k] * W[k * 32 + c];
    g_h2l[t] = s;
}

__global__ void k_att2d(const float* __restrict__ a2s, const float* __restrict__ a2d) {
    int n = blockIdx.x * blockDim.x + threadIdx.x;           // over NN
    if (n >= NN) return;
    float s = 0.f, d = 0.f;
    for (int c = 0; c < 32; c++) {
        float v = g_h2l[(size_t)n * 32 + c];
        s += v * a2s[c];
        d += v * a2d[c];
    }
    g_als2[n] = s; g_ald2[n] = d;
}

__global__ void k_ale2(const float* __restrict__ ea, const float* __restrict__ W2e,
                       const float* __restrict__ a2e) {
    int e = blockIdx.x * blockDim.x + threadIdx.x;           // over EP
    if (e >= EP) return;
    const float* attr = (e < EE) ? (ea + (size_t)e * 16) : (g_mean + (size_t)(e - EE) * 16);
    float al = 0.f;
    for (int c = 0; c < 32; c++) {
        float he = 0.f;
        for (int ed = 0; ed < 16; ed++)
            he += attr[ed] * W2e[ed * 32 + c];
        al += he * a2e[c];
    }
    g_ale2[e] = al;
}

__global__ void k_e2(const int* __restrict__ ei) {
    int e = blockIdx.x * blockDim.x + threadIdx.x;           // over EP
    if (e >= EP) return;
    int s, d;
    if (e < EE) { s = ei[e]; d = ei[EE + e]; } else { s = e - EE; d = s; }
    float p = expf(lrelu(g_als2[s] + g_ald2[d] + g_ale2[e]));
    g_p2[e] = p;
    atomicAdd(&g_z2[d], p);
}

__global__ void k_g2(const int* __restrict__ ei, float* __restrict__ alphaOut) {
    int t = blockIdx.x * blockDim.x + threadIdx.x;           // over EP*32
    if (t >= EP * 32) return;
    int e = t >> 5, c = t & 31;
    int s, d;
    if (e < EE) { s = ei[e]; d = ei[EE + e]; } else { s = e - EE; d = s; }
    float alpha = g_p2[e] / g_z2[d];
    atomicAdd(&g_agg2[(size_t)d * 32 + c], alpha * g_h2l[(size_t)s * 32 + c]);
    if (c == 0 && alphaOut) alphaOut[e] = alpha;
}

__global__ void k_out(const float* __restrict__ b2, float* __restrict__ out) {
    int t = blockIdx.x * blockDim.x + threadIdx.x;           // over NN*32
    if (t >= NN * 32) return;
    out[t] = elu(g_agg2[t] + b2[t & 31]);
}

// ---------------- edge_index_sl output (as float) ----------------
__global__ void k_eidx(const int* __restrict__ ei, float* __restrict__ out) {
    int t = blockIdx.x * blockDim.x + threadIdx.x;
    if (t >= 2 * EP) return;
    int row = t / EP, j = t - row * EP;
    int v = (j < EE) ? ei[row * EE + j] : (j - EE);
    out[(size_t)NN * 32 + t] = (float)v;
}

// ---------------- launch ----------------
extern "C" void kernel_launch(void* const* d_in, const int* in_sizes, int n_in,
                              void* d_out, int out_size) {
    // Resolve input ordering defensively by sizes. Default: dict/insertion order.
    // If in_sizes[0] == 16384 (W1 first), assume pytree-alphabetical order.
    int ix, iei, iea, iW1, iW1e, ia1s, ia1d, ia1e, ib1, iW2, iW2e, ia2s, ia2d, ia2e, ib2;
    if (n_in >= 15 && in_sizes[0] == 16384) {
        // alphabetical: W1 W1e W2 W2e a1_dst a1_edge a1_src a2_dst a2_edge a2_src b1 b2 edge_attr edge_index x
        iW1 = 0; iW1e = 1; iW2 = 2; iW2e = 3;
        ia1d = 4; ia1e = 5; ia1s = 6;
        ia2d = 7; ia2e = 8; ia2s = 9;
        ib1 = 10; ib2 = 11; iea = 12; iei = 13; ix = 14;
    } else {
        // dict order: x edge_index edge_attr W1 W1e a1_src a1_dst a1_edge b1 W2 W2e a2_src a2_dst a2_edge b2
        ix = 0; iei = 1; iea = 2; iW1 = 3; iW1e = 4;
        ia1s = 5; ia1d = 6; ia1e = 7; ib1 = 8;
        iW2 = 9; iW2e = 10; ia2s = 11; ia2d = 12; ia2e = 13; ib2 = 14;
    }
    const float* x   = (const float*)d_in[ix];
    const int*   ei  = (const int*)d_in[iei];
    const float* ea  = (const float*)d_in[iea];
    const float* W1  = (const float*)d_in[iW1];
    const float* W1e = (const float*)d_in[iW1e];
    const float* a1s = (const float*)d_in[ia1s];
    const float* a1d = (const float*)d_in[ia1d];
    const float* a1e = (const float*)d_in[ia1e];
    const float* b1  = (const float*)d_in[ib1];
    const float* W2  = (const float*)d_in[iW2];
    const float* W2e = (const float*)d_in[iW2e];
    const float* a2s = (const float*)d_in[ia2s];
    const float* a2d = (const float*)d_in[ia2d];
    const float* a2e = (const float*)d_in[ia2e];
    const float* b2  = (const float*)d_in[ib2];
    float* out = (float*)d_out;

    bool full = (out_size >= NN * 32 + 3 * EP);
    float* alphaOut = full ? out + (size_t)NN * 32 + 2 * (size_t)EP : nullptr;

    const int B = 256;
    kz<<<(NN * 128 + B - 1) / B, B>>>();
    k_outzero<<<(out_size + B - 1) / B, B>>>(out, out_size);
    k_deg<<<(EE + B - 1) / B, B>>>(ei, ea);
    k_mean<<<(NN * 16 + B - 1) / B, B>>>();
    k_gemm1d<<<(NN * 128 + B - 1) / B, B>>>(x, W1);
    k_att1d<<<(NN * 4 + B - 1) / B, B>>>(a1s, a1d);
    k_ale1<<<(EP * 4 + B - 1) / B, B>>>(ea, W1e, a1e);
    k_e1<<<(EP * 4 + B - 1) / B, B>>>(ei);
    k_g1<<<(int)(((size_t)EP * 128 + B - 1) / B), B>>>(ei);
    k_h1o<<<(NN * 128 + B - 1) / B, B>>>(b1);
    k_gemm2d<<<(NN * 32 + B - 1) / B, B>>>(W2);
    k_att2d<<<(NN + B - 1) / B, B>>>(a2s, a2d);
    k_ale2<<<(EP + B - 1) / B, B>>>(ea, W2e, a2e);
    k_e2<<<(EP + B - 1) / B, B>>>(ei);
    k_g2<<<(int)(((size_t)EP * 32 + B - 1) / B), B>>>(ei, alphaOut);
    k_out<<<(NN * 32 + B - 1) / B, B>>>(b2, out);
    if (full) k_eidx<<<(2 * EP + B - 1) / B, B>>>(ei, out);
}

// round 8
// speedup vs baseline: 1.3539x; 1.3539x over previous
#include <cuda_runtime.h>

#define NN 100000
#define EE 1600000
#define EP (EE + NN)
#define NBLK ((NN + 1023) / 1024)   // 98
#define NEG 0.2f
#define NINF (-1e30f)

// ---------------- scratch (static device globals; no allocation) ----------------
__device__ int   g_deg[NN];
__device__ float g_sumattr[NN * 16];
__device__ float g_mean[NN * 16];
__device__ int   g_cursor[NN];
__device__ int   g_offsets[NN + 1];
__device__ int   g_partials[NBLK + 2];
__device__ int   g_csrc[EP];                   // CSR: source node per slot
__device__ int   g_ceid[EP];                   // CSR: original edge id per slot
__device__ float g_h1[(size_t)NN * 128];
__device__ float g_als1[NN * 4];
__device__ float g_ald1[NN * 4];
__device__ float g_ale1[(size_t)EP * 4];       // per-ORIGINAL-edge layer-1 edge score
__device__ float g_alpha1[(size_t)EP * 4];     // per-CSR-slot softmax weight
__device__ float g_h1o[(size_t)NN * 128];
__device__ float g_h2l[(size_t)NN * 32];
__device__ float g_als2[NN];
__device__ float g_ald2[NN];
__device__ float g_ale2[EP];                   // per-ORIGINAL-edge layer-2 edge score
__device__ float g_alpha2[EP];                 // per-CSR-slot softmax weight

__device__ __forceinline__ float lrelu(float x) { return x > 0.f ? x : NEG * x; }
__device__ __forceinline__ float elu(float x)   { return x > 0.f ? x : expm1f(x); }

// ---------------- init (identical to passing round-5 where applicable) ----------------
__global__ void kz() {
    int i = blockIdx.x * blockDim.x + threadIdx.x;           // over NN*16
    if (i < NN) { g_deg[i] = 0; g_cursor[i] = 0; }
    if (i < NN * 16) g_sumattr[i] = 0.f;
}

__global__ void k_outzero(float* out, int n) {
    int i = blockIdx.x * blockDim.x + threadIdx.x;
    if (i < n) out[i] = 0.f;
}

// ---------------- degree + edge-attr sums per dst (verbatim round 5) ----------------
__global__ void k_deg(const int* __restrict__ ei, const float* __restrict__ ea) {
    int e = blockIdx.x * blockDim.x + threadIdx.x;
    if (e >= EE) return;
    int d = ei[EE + e];
    atomicAdd(&g_deg[d], 1);
    for (int j = 0; j < 16; j++)
        atomicAdd(&g_sumattr[d * 16 + j], ea[(size_t)e * 16 + j]);
}

__global__ void k_mean() {
    int t = blockIdx.x * blockDim.x + threadIdx.x;           // over NN*16
    if (t >= NN * 16) return;
    int n = t >> 4;
    g_mean[t] = g_sumattr[t] / fmaxf((float)g_deg[n], 1.f);
}

// ---------------- 3-kernel exclusive scan of counts = deg+1 ----------------
__global__ void k_scan1() {
    __shared__ int sh[1024];
    int tid = threadIdx.x;
    int i = blockIdx.x * 1024 + tid;
    int v = (i < NN) ? (g_deg[i] + 1) : 0;
    sh[tid] = v;
    __syncthreads();
    for (int off = 1; off < 1024; off <<= 1) {
        int t = 0;
        if (tid >= off) t = sh[tid - off];
        __syncthreads();
        sh[tid] += t;
        __syncthreads();
    }
    if (i < NN) g_offsets[i] = sh[tid] - v;       // exclusive within block
    if (tid == 1023) g_partials[blockIdx.x] = sh[1023];
}
__global__ void k_scan2() {
    int run = 0;
    for (int b = 0; b < NBLK; b++) { int t = g_partials[b]; g_partials[b] = run; run += t; }
    g_partials[NBLK] = run;
}
__global__ void k_scan3() {
    int i = blockIdx.x * blockDim.x + threadIdx.x;
    if (i > NN) return;
    if (i == NN) g_offsets[NN] = g_partials[NBLK];
    else g_offsets[i] += g_partials[i >> 10];
}

// ---------------- CSR scatter: src + eid only ----------------
__global__ void k_scatter(const int* __restrict__ ei) {
    int t = blockIdx.x * blockDim.x + threadIdx.x;
    if (t >= EP) return;
    int s, d;
    if (t < EE) { s = ei[t]; d = ei[EE + t]; }
    else        { s = t - EE; d = s; }
    int pos = g_offsets[d] + atomicAdd(&g_cursor[d], 1);
    g_csrc[pos] = s;
    g_ceid[pos] = t;
}

// ---------------- dumb GEMM1 (verbatim round 5) ----------------
__global__ void k_gemm1d(const float* __restrict__ X, const float* __restrict__ W) {
    int t = blockIdx.x * blockDim.x + threadIdx.x;           // over NN*128
    if (t >= NN * 128) return;
    int n = t >> 7, j = t & 127;
    float s = 0.f;
    for (int k = 0; k < 128; k++)
        s += X[(size_t)n * 128 + k] * W[k * 128 + j];
    g_h1[t] = s;
}

// ---------------- attention dots (verbatim round 5) ----------------
__global__ void k_att1d(const float* __restrict__ a1s, const float* __restrict__ a1d) {
    int t = blockIdx.x * blockDim.x + threadIdx.x;           // over NN*4
    if (t >= NN * 4) return;
    int n = t >> 2, h = t & 3;
    float s = 0.f, d = 0.f;
    for (int c = 0; c < 32; c++) {
        float v = g_h1[(size_t)n * 128 + h * 32 + c];
        s += v * a1s[h * 32 + c];
        d += v * a1d[h * 32 + c];
    }
    g_als1[t] = s; g_ald1[t] = d;
}

// ---------------- layer-1 edge-feature attention term (verbatim round 5) ----------------
__global__ void k_ale1(const float* __restrict__ ea, const float* __restrict__ W1e,
                       const float* __restrict__ a1e) {
    int t = blockIdx.x * blockDim.x + threadIdx.x;           // over EP*4
    if (t >= EP * 4) return;
    int e = t >> 2, h = t & 3;
    const float* attr = (e < EE) ? (ea + (size_t)e * 16) : (g_mean + (size_t)(e - EE) * 16);
    float al = 0.f;
    for (int c = 0; c < 32; c++) {
        float he = 0.f;
        for (int ed = 0; ed < 16; ed++)
            he += attr[ed] * W1e[ed * 128 + h * 32 + c];
        al += he * a1e[h * 32 + c];
    }
    g_ale1[t] = al;
}

// ---------------- layer-1 softmax: warp per (node,head), logits by original eid ----------------
__global__ void k_walpha1() {
    int gw = (blockIdx.x * blockDim.x + threadIdx.x) >> 5;
    int lane = threadIdx.x & 31;
    if (gw >= NN * 4) return;
    int n = gw >> 2, h = gw & 3;
    int st = g_offsets[n], en = g_offsets[n + 1];
    float ald = g_ald1[n * 4 + h];
    float m = NINF;
    for (int i = st + lane; i < en; i += 32) {
        int s = g_csrc[i], eid = g_ceid[i];
        float e = lrelu(g_als1[s * 4 + h] + ald + g_ale1[(size_t)eid * 4 + h]);
        m = fmaxf(m, e);
    }
    #pragma unroll
    for (int o = 16; o; o >>= 1) m = fmaxf(m, __shfl_xor_sync(~0u, m, o));
    float z = 0.f;
    for (int i = st + lane; i < en; i += 32) {
        int s = g_csrc[i], eid = g_ceid[i];
        float e = lrelu(g_als1[s * 4 + h] + ald + g_ale1[(size_t)eid * 4 + h]);
        z += expf(e - m);
    }
    #pragma unroll
    for (int o = 16; o; o >>= 1) z += __shfl_xor_sync(~0u, z, o);
    float invz = 1.f / z;
    for (int i = st + lane; i < en; i += 32) {
        int s = g_csrc[i], eid = g_ceid[i];
        float e = lrelu(g_als1[s * 4 + h] + ald + g_ale1[(size_t)eid * 4 + h]);
        g_alpha1[(size_t)i * 4 + h] = expf(e - m) * invz;
    }
}

// ---------------- layer-1 gather: warp per node ----------------
__global__ void k_wgather1(const float* __restrict__ b1) {
    int wid = (blockIdx.x * blockDim.x + threadIdx.x) >> 5;
    int lane = threadIdx.x & 31;
    if (wid >= NN) return;
    int st = g_offsets[wid], en = g_offsets[wid + 1];
    int h = lane >> 3;        // channels lane*4..lane*4+3 all in head (lane*4)/32
    float4 acc = make_float4(0.f, 0.f, 0.f, 0.f);
    for (int i = st; i < en; i++) {
        int s = g_csrc[i];
        float a = g_alpha1[(size_t)i * 4 + h];
        float4 hv = *(const float4*)&g_h1[(size_t)s * 128 + lane * 4];
        acc.x += a * hv.x; acc.y += a * hv.y;
        acc.z += a * hv.z; acc.w += a * hv.w;
    }
    int j = lane * 4;
    float4 o;
    o.x = elu(acc.x + b1[j+0]); o.y = elu(acc.y + b1[j+1]);
    o.z = elu(acc.z + b1[j+2]); o.w = elu(acc.w + b1[j+3]);
    *(float4*)&g_h1o[(size_t)wid * 128 + j] = o;
}

// ---------------- dumb GEMM2 (verbatim round 5) ----------------
__global__ void k_gemm2d(const float* __restrict__ W) {
    int t = blockIdx.x * blockDim.x + threadIdx.x;           // over NN*32
    if (t >= NN * 32) return;
    int n = t >> 5, c = t & 31;
    float s = 0.f;
    for (int k = 0; k < 128; k++)
        s += g_h1o[(size_t)n * 128 + k] * W[k * 32 + c];
    g_h2l[t] = s;
}

__global__ void k_att2d(const float* __restrict__ a2s, const float* __restrict__ a2d) {
    int n = blockIdx.x * blockDim.x + threadIdx.x;           // over NN
    if (n >= NN) return;
    float s = 0.f, d = 0.f;
    for (int c = 0; c < 32; c++) {
        float v = g_h2l[(size_t)n * 32 + c];
        s += v * a2s[c];
        d += v * a2d[c];
    }
    g_als2[n] = s; g_ald2[n] = d;
}

__global__ void k_ale2(const float* __restrict__ ea, const float* __restrict__ W2e,
                       const float* __restrict__ a2e) {
    int e = blockIdx.x * blockDim.x + threadIdx.x;           // over EP
    if (e >= EP) return;
    const float* attr = (e < EE) ? (ea + (size_t)e * 16) : (g_mean + (size_t)(e - EE) * 16);
    float al = 0.f;
    for (int c = 0; c < 32; c++) {
        float he = 0.f;
        for (int ed = 0; ed < 16; ed++)
            he += attr[ed] * W2e[ed * 32 + c];
        al += he * a2e[c];
    }
    g_ale2[e] = al;
}

// ---------------- layer-2 softmax: warp per node ----------------
__global__ void k_walpha2(float* __restrict__ outAlpha) {
    int wid = (blockIdx.x * blockDim.x + threadIdx.x) >> 5;
    int lane = threadIdx.x & 31;
    if (wid >= NN) return;
    int st = g_offsets[wid], en = g_offsets[wid + 1];
    float ald = g_ald2[wid];
    float m = NINF;
    for (int i = st + lane; i < en; i += 32) {
        int s = g_csrc[i], eid = g_ceid[i];
        m = fmaxf(m, lrelu(g_als2[s] + ald + g_ale2[eid]));
    }
    #pragma unroll
    for (int o = 16; o; o >>= 1) m = fmaxf(m, __shfl_xor_sync(~0u, m, o));
    float z = 0.f;
    for (int i = st + lane; i < en; i += 32) {
        int s = g_csrc[i], eid = g_ceid[i];
        z += expf(lrelu(g_als2[s] + ald + g_ale2[eid]) - m);
    }
    #pragma unroll
    for (int o = 16; o; o >>= 1) z += __shfl_xor_sync(~0u, z, o);
    float invz = 1.f / z;
    for (int i = st + lane; i < en; i += 32) {
        int s = g_csrc[i], eid = g_ceid[i];
        float a = expf(lrelu(g_als2[s] + ald + g_ale2[eid]) - m) * invz;
        g_alpha2[i] = a;
        if (outAlpha) outAlpha[eid] = a;
    }
}

// ---------------- layer-2 gather: warp per node (lane = channel) ----------------
__global__ void k_wgather2(const float* __restrict__ b2, float* __restrict__ outH2) {
    int wid = (blockIdx.x * blockDim.x + threadIdx.x) >> 5;
    int lane = threadIdx.x & 31;
    if (wid >= NN) return;
    int st = g_offsets[wid], en = g_offsets[wid + 1];
    float acc = 0.f;
    for (int i = st; i < en; i++) {
        int s = g_csrc[i];
        acc += g_alpha2[i] * g_h2l[(size_t)s * 32 + lane];
    }
    outH2[wid * 32 + lane] = elu(acc + b2[lane]);
}

// ---------------- edge_index_sl output (as float) ----------------
__global__ void k_eidx(const int* __restrict__ ei, float* __restrict__ out) {
    int t = blockIdx.x * blockDim.x + threadIdx.x;
    if (t >= 2 * EP) return;
    int row = t / EP, j = t - row * EP;
    int v = (j < EE) ? ei[row * EE + j] : (j - EE);
    out[(size_t)NN * 32 + t] = (float)v;
}

// ---------------- launch ----------------
extern "C" void kernel_launch(void* const* d_in, const int* in_sizes, int n_in,
                              void* d_out, int out_size) {
    // Inputs confirmed to be in dict order (resolver branch never fired); keep it anyway.
    int ix, iei, iea, iW1, iW1e, ia1s, ia1d, ia1e, ib1, iW2, iW2e, ia2s, ia2d, ia2e, ib2;
    if (n_in >= 15 && in_sizes[0] == 16384) {
        iW1 = 0; iW1e = 1; iW2 = 2; iW2e = 3;
        ia1d = 4; ia1e = 5; ia1s = 6;
        ia2d = 7; ia2e = 8; ia2s = 9;
        ib1 = 10; ib2 = 11; iea = 12; iei = 13; ix = 14;
    } else {
        ix = 0; iei = 1; iea = 2; iW1 = 3; iW1e = 4;
        ia1s = 5; ia1d = 6; ia1e = 7; ib1 = 8;
        iW2 = 9; iW2e = 10; ia2s = 11; ia2d = 12; ia2e = 13; ib2 = 14;
    }
    const float* x   = (const float*)d_in[ix];
    const int*   ei  = (const int*)d_in[iei];
    const float* ea  = (const float*)d_in[iea];
    const float* W1  = (const float*)d_in[iW1];
    const float* W1e = (const float*)d_in[iW1e];
    const float* a1s = (const float*)d_in[ia1s];
    const float* a1d = (const float*)d_in[ia1d];
    const float* a1e = (const float*)d_in[ia1e];
    const float* b1  = (const float*)d_in[ib1];
    const float* W2  = (const float*)d_in[iW2];
    const float* W2e = (const float*)d_in[iW2e];
    const float* a2s = (const float*)d_in[ia2s];
    const float* a2d = (const float*)d_in[ia2d];
    const float* a2e = (const float*)d_in[ia2e];
    const float* b2  = (const float*)d_in[ib2];
    float* out = (float*)d_out;

    bool full = (out_size >= NN * 32 + 3 * EP);
    float* alphaOut = full ? out + (size_t)NN * 32 + 2 * (size_t)EP : nullptr;

    const int B = 256;
    kz<<<(NN * 16 + B - 1) / B, B>>>();
    k_outzero<<<(out_size + B - 1) / B, B>>>(out, out_size);
    k_deg<<<(EE + B - 1) / B, B>>>(ei, ea);
    k_mean<<<(NN * 16 + B - 1) / B, B>>>();
    k_scan1<<<NBLK, 1024>>>();
    k_scan2<<<1, 1>>>();
    k_scan3<<<(NN + 1 + B - 1) / B, B>>>();
    k_scatter<<<(EP + B - 1) / B, B>>>(ei);
    k_gemm1d<<<(NN * 128 + B - 1) / B, B>>>(x, W1);
    k_att1d<<<(NN * 4 + B - 1) / B, B>>>(a1s, a1d);
    k_ale1<<<(EP * 4 + B - 1) / B, B>>>(ea, W1e, a1e);
    k_walpha1<<<(NN * 4 * 32 + B - 1) / B, B>>>();           // warp per (node,head)
    k_wgather1<<<(NN * 32 + B - 1) / B, B>>>(b1);            // warp per node
    k_gemm2d<<<(NN * 32 + B - 1) / B, B>>>(W2);
    k_att2d<<<(NN + B - 1) / B, B>>>(a2s, a2d);
    k_ale2<<<(EP + B - 1) / B, B>>>(ea, W2e, a2e);
    k_walpha2<<<(NN * 32 + B - 1) / B, B>>>(alphaOut);       // warp per node
    k_wgather2<<<(NN * 32 + B - 1) / B, B>>>(b2, out);       // warp per node
    if (full) k_eidx<<<(2 * EP + B - 1) / B, B>>>(ei, out);
}

// round 11
// speedup vs baseline: 3.7602x; 2.7773x over previous
#include <cuda_runtime.h>

#define NN 100000
#define EE 1600000
#define EP (EE + NN)
#define NBLK ((NN + 1023) / 1024)   // 98
#define NEG 0.2f
#define NINF (-1e30f)

// ---------------- scratch (static device globals; no allocation) ----------------
__device__ int   g_deg[NN];
__device__ float g_sum1[NN * 4];
__device__ float g_sum2[NN];
__device__ int   g_cursor[NN];
__device__ int   g_offsets[NN + 1];
__device__ int   g_partials[NBLK + 2];
__device__ int   g_csrc[EP];                   // CSR: source node per slot
__device__ int   g_ceid[EP];                   // CSR: original edge id per slot
__device__ float g_h1[(size_t)NN * 128];
__device__ float g_als1[NN * 4];
__device__ float g_ald1[NN * 4];
__device__ float g_ale1[(size_t)EP * 4];       // per-ORIGINAL-edge layer-1 edge score
__device__ float g_alpha1[(size_t)EP * 4];     // per-CSR-slot softmax weight
__device__ float g_h1o[(size_t)NN * 128];
__device__ float g_h2l[(size_t)NN * 32];
__device__ float g_als2[NN];
__device__ float g_ald2[NN];
__device__ float g_ale2[EP];                   // per-ORIGINAL-edge layer-2 edge score
__device__ float g_alpha2[EP];                 // per-CSR-slot softmax weight
__device__ float g_v1[64];                     // folded W1e*a1e: [16 ed][4 h]
__device__ float g_v2[16];                     // folded W2e*a2e

__device__ __forceinline__ float lrelu(float x) { return x > 0.f ? x : NEG * x; }
__device__ __forceinline__ float elu(float x)   { return x > 0.f ? x : expm1f(x); }

// ---------------- init ----------------
__global__ void kz() {
    int i = blockIdx.x * blockDim.x + threadIdx.x;           // over NN*4
    if (i < NN) { g_deg[i] = 0; g_cursor[i] = 0; g_sum2[i] = 0.f; }
    if (i < NN * 4) g_sum1[i] = 0.f;
}

__global__ void k_outzero(float* out, int n) {
    int i = blockIdx.x * blockDim.x + threadIdx.x;
    if (i < n) out[i] = 0.f;
}

// fold W_e with a_edge:  v1[ed][h] = sum_c W1e[ed, h*32+c] * a1e[h*32+c];  v2 likewise
__global__ void k_prep(const float* __restrict__ W1e, const float* __restrict__ a1e,
                       const float* __restrict__ W2e, const float* __restrict__ a2e) {
    int t = threadIdx.x;
    if (t < 64) {
        int ed = t >> 2, h = t & 3;
        float s = 0.f;
        for (int c = 0; c < 32; c++) s += W1e[ed * 128 + h * 32 + c] * a1e[h * 32 + c];
        g_v1[t] = s;
    } else if (t < 80) {
        int ed = t - 64;
        float s = 0.f;
        for (int c = 0; c < 32; c++) s += W2e[ed * 32 + c] * a2e[c];
        g_v2[ed] = s;
    }
}

// ---------------- fused: per-edge folded scores + degree + self-loop score sums ----------------
__global__ void k_edge(const int* __restrict__ ei, const float* __restrict__ ea) {
    __shared__ float v1[64], v2[16];
    int t = threadIdx.x;
    if (t < 64) v1[t] = g_v1[t];
    if (t < 16) v2[t] = g_v2[t];
    __syncthreads();
    int e = blockIdx.x * blockDim.x + t;
    if (e >= EE) return;
    int d = ei[EE + e];
    atomicAdd(&g_deg[d], 1);
    float a[16];
    const float4* ep = (const float4*)(ea + (size_t)e * 16);
    float4 q0 = ep[0], q1 = ep[1], q2 = ep[2], q3 = ep[3];
    a[0]=q0.x;a[1]=q0.y;a[2]=q0.z;a[3]=q0.w; a[4]=q1.x;a[5]=q1.y;a[6]=q1.z;a[7]=q1.w;
    a[8]=q2.x;a[9]=q2.y;a[10]=q2.z;a[11]=q2.w; a[12]=q3.x;a[13]=q3.y;a[14]=q3.z;a[15]=q3.w;
    float s0=0,s1=0,s2=0,s3=0,u=0;
    #pragma unroll
    for (int k = 0; k < 16; k++) {
        float x = a[k];
        s0 += x * v1[k*4+0]; s1 += x * v1[k*4+1];
        s2 += x * v1[k*4+2]; s3 += x * v1[k*4+3];
        u  += x * v2[k];
    }
    size_t e4 = (size_t)e * 4;
    g_ale1[e4+0]=s0; g_ale1[e4+1]=s1; g_ale1[e4+2]=s2; g_ale1[e4+3]=s3;
    g_ale2[e] = u;
    atomicAdd(&g_sum1[d*4+0], s0); atomicAdd(&g_sum1[d*4+1], s1);
    atomicAdd(&g_sum1[d*4+2], s2); atomicAdd(&g_sum1[d*4+3], s3);
    atomicAdd(&g_sum2[d], u);
}

// self-loop scores = mean of incoming per-edge scores (linearity of the edge term)
__global__ void k_slscore() {
    int t = blockIdx.x * blockDim.x + threadIdx.x;           // over NN*4
    if (t >= NN * 4) return;
    int i = t >> 2;
    float inv = 1.f / fmaxf((float)g_deg[i], 1.f);
    g_ale1[(size_t)(EE + i) * 4 + (t & 3)] = g_sum1[t] * inv;
    if ((t & 3) == 0) g_ale2[EE + i] = g_sum2[i] * inv;
}

// ---------------- 3-kernel exclusive scan of counts = deg+1 (verbatim round 8) ----------------
__global__ void k_scan1() {
    __shared__ int sh[1024];
    int tid = threadIdx.x;
    int i = blockIdx.x * 1024 + tid;
    int v = (i < NN) ? (g_deg[i] + 1) : 0;
    sh[tid] = v;
    __syncthreads();
    for (int off = 1; off < 1024; off <<= 1) {
        int t = 0;
        if (tid >= off) t = sh[tid - off];
        __syncthreads();
        sh[tid] += t;
        __syncthreads();
    }
    if (i < NN) g_offsets[i] = sh[tid] - v;       // exclusive within block
    if (tid == 1023) g_partials[blockIdx.x] = sh[1023];
}
__global__ void k_scan2() {
    int run = 0;
    for (int b = 0; b < NBLK; b++) { int t = g_partials[b]; g_partials[b] = run; run += t; }
    g_partials[NBLK] = run;
}
__global__ void k_scan3() {
    int i = blockIdx.x * blockDim.x + threadIdx.x;
    if (i > NN) return;
    if (i == NN) g_offsets[NN] = g_partials[NBLK];
    else g_offsets[i] += g_partials[i >> 10];
}

// ---------------- CSR scatter: src + eid only (verbatim round 8) ----------------
__global__ void k_scatter(const int* __restrict__ ei) {
    int t = blockIdx.x * blockDim.x + threadIdx.x;
    if (t >= EP) return;
    int s, d;
    if (t < EE) { s = ei[t]; d = ei[EE + t]; }
    else        { s = t - EE; d = s; }
    int pos = g_offsets[d] + atomicAdd(&g_cursor[d], 1);
    g_csrc[pos] = s;
    g_ceid[pos] = t;
}

// ---------------- dumb GEMM1 (verbatim round 8) ----------------
__global__ void k_gemm1d(const float* __restrict__ X, const float* __restrict__ W) {
    int t = blockIdx.x * blockDim.x + threadIdx.x;           // over NN*128
    if (t >= NN * 128) return;
    int n = t >> 7, j = t & 127;
    float s = 0.f;
    for (int k = 0; k < 128; k++)
        s += X[(size_t)n * 128 + k] * W[k * 128 + j];
    g_h1[t] = s;
}

// ---------------- attention dots (verbatim round 8) ----------------
__global__ void k_att1d(const float* __restrict__ a1s, const float* __restrict__ a1d) {
    int t = blockIdx.x * blockDim.x + threadIdx.x;           // over NN*4
    if (t >= NN * 4) return;
    int n = t >> 2, h = t & 3;
    float s = 0.f, d = 0.f;
    for (int c = 0; c < 32; c++) {
        float v = g_h1[(size_t)n * 128 + h * 32 + c];
        s += v * a1s[h * 32 + c];
        d += v * a1d[h * 32 + c];
    }
    g_als1[t] = s; g_ald1[t] = d;
}

// ---------------- layer-1 softmax: warp per (node,head), logits by original eid ----------------
__global__ void k_walpha1() {
    int gw = (blockIdx.x * blockDim.x + threadIdx.x) >> 5;
    int lane = threadIdx.x & 31;
    if (gw >= NN * 4) return;
    int n = gw >> 2, h = gw & 3;
    int st = g_offsets[n], en = g_offsets[n + 1];
    float ald = g_ald1[n * 4 + h];
    float m = NINF;
    for (int i = st + lane; i < en; i += 32) {
        int s = g_csrc[i], eid = g_ceid[i];
        float e = lrelu(g_als1[s * 4 + h] + ald + g_ale1[(size_t)eid * 4 + h]);
        m = fmaxf(m, e);
    }
    #pragma unroll
    for (int o = 16; o; o >>= 1) m = fmaxf(m, __shfl_xor_sync(~0u, m, o));
    float z = 0.f;
    for (int i = st + lane; i < en; i += 32) {
        int s = g_csrc[i], eid = g_ceid[i];
        float e = lrelu(g_als1[s * 4 + h] + ald + g_ale1[(size_t)eid * 4 + h]);
        z += expf(e - m);
    }
    #pragma unroll
    for (int o = 16; o; o >>= 1) z += __shfl_xor_sync(~0u, z, o);
    float invz = 1.f / z;
    for (int i = st + lane; i < en; i += 32) {
        int s = g_csrc[i], eid = g_ceid[i];
        float e = lrelu(g_als1[s * 4 + h] + ald + g_ale1[(size_t)eid * 4 + h]);
        g_alpha1[(size_t)i * 4 + h] = expf(e - m) * invz;
    }
}

// ---------------- layer-1 gather: warp per node (verbatim round 8) ----------------
__global__ void k_wgather1(const float* __restrict__ b1) {
    int wid = (blockIdx.x * blockDim.x + threadIdx.x) >> 5;
    int lane = threadIdx.x & 31;
    if (wid >= NN) return;
    int st = g_offsets[wid], en = g_offsets[wid + 1];
    int h = lane >> 3;        // channels lane*4..lane*4+3 all in head (lane*4)/32
    float4 acc = make_float4(0.f, 0.f, 0.f, 0.f);
    for (int i = st; i < en; i++) {
        int s = g_csrc[i];
        float a = g_alpha1[(size_t)i * 4 + h];
        float4 hv = *(const float4*)&g_h1[(size_t)s * 128 + lane * 4];
        acc.x += a * hv.x; acc.y += a * hv.y;
        acc.z += a * hv.z; acc.w += a * hv.w;
    }
    int j = lane * 4;
    float4 o;
    o.x = elu(acc.x + b1[j+0]); o.y = elu(acc.y + b1[j+1]);
    o.z = elu(acc.z + b1[j+2]); o.w = elu(acc.w + b1[j+3]);
    *(float4*)&g_h1o[(size_t)wid * 128 + j] = o;
}

// ---------------- dumb GEMM2 (verbatim round 8) ----------------
__global__ void k_gemm2d(const float* __restrict__ W) {
    int t = blockIdx.x * blockDim.x + threadIdx.x;           // over NN*32
    if (t >= NN * 32) return;
    int n = t >> 5, c = t & 31;
    float s = 0.f;
    for (int k = 0; k < 128; k++)
        s += g_h1o[(size_t)n * 128 + k] * W[k * 32 + c];
    g_h2l[t] = s;
}

__global__ void k_att2d(const float* __restrict__ a2s, const float* __restrict__ a2d) {
    int n = blockIdx.x * blockDim.x + threadIdx.x;           // over NN
    if (n >= NN) return;
    float s = 0.f, d = 0.f;
    for (int c = 0; c < 32; c++) {
        float v = g_h2l[(size_t)n * 32 + c];
        s += v * a2s[c];
        d += v * a2d[c];
    }
    g_als2[n] = s; g_ald2[n] = d;
}

// ---------------- layer-2 softmax: warp per node (verbatim round 8) ----------------
__global__ void k_walpha2(float* __restrict__ outAlpha) {
    int wid = (blockIdx.x * blockDim.x + threadIdx.x) >> 5;
    int lane = threadIdx.x & 31;
    if (wid >= NN) return;
    int st = g_offsets[wid], en = g_offsets[wid + 1];
    float ald = g_ald2[wid];
    float m = NINF;
    for (int i = st + lane; i < en; i += 32) {
        int s = g_csrc[i], eid = g_ceid[i];
        m = fmaxf(m, lrelu(g_als2[s] + ald + g_ale2[eid]));
    }
    #pragma unroll
    for (int o = 16; o; o >>= 1) m = fmaxf(m, __shfl_xor_sync(~0u, m, o));
    float z = 0.f;
    for (int i = st + lane; i < en; i += 32) {
        int s = g_csrc[i], eid = g_ceid[i];
        z += expf(lrelu(g_als2[s] + ald + g_ale2[eid]) - m);
    }
    #pragma unroll
    for (int o = 16; o; o >>= 1) z += __shfl_xor_sync(~0u, z, o);
    float invz = 1.f / z;
    for (int i = st + lane; i < en; i += 32) {
        int s = g_csrc[i], eid = g_ceid[i];
        float a = expf(lrelu(g_als2[s] + ald + g_ale2[eid]) - m) * invz;
        g_alpha2[i] = a;
        if (outAlpha) outAlpha[eid] = a;
    }
}

// ---------------- layer-2 gather: warp per node (verbatim round 8) ----------------
__global__ void k_wgather2(const float* __restrict__ b2, float* __restrict__ outH2) {
    int wid = (blockIdx.x * blockDim.x + threadIdx.x) >> 5;
    int lane = threadIdx.x & 31;
    if (wid >= NN) return;
    int st = g_offsets[wid], en = g_offsets[wid + 1];
    float acc = 0.f;
    for (int i = st; i < en; i++) {
        int s = g_csrc[i];
        acc += g_alpha2[i] * g_h2l[(size_t)s * 32 + lane];
    }
    outH2[wid * 32 + lane] = elu(acc + b2[lane]);
}

// ---------------- edge_index_sl output (as float) ----------------
__global__ void k_eidx(const int* __restrict__ ei, float* __restrict__ out) {
    int t = blockIdx.x * blockDim.x + threadIdx.x;
    if (t >= 2 * EP) return;
    int row = t / EP, j = t - row * EP;
    int v = (j < EE) ? ei[row * EE + j] : (j - EE);
    out[(size_t)NN * 32 + t] = (float)v;
}

// ---------------- launch ----------------
extern "C" void kernel_launch(void* const* d_in, const int* in_sizes, int n_in,
                              void* d_out, int out_size) {
    int ix, iei, iea, iW1, iW1e, ia1s, ia1d, ia1e, ib1, iW2, iW2e, ia2s, ia2d, ia2e, ib2;
    if (n_in >= 15 && in_sizes[0] == 16384) {
        iW1 = 0; iW1e = 1; iW2 = 2; iW2e = 3;
        ia1d = 4; ia1e = 5; ia1s = 6;
        ia2d = 7; ia2e = 8; ia2s = 9;
        ib1 = 10; ib2 = 11; iea = 12; iei = 13; ix = 14;
    } else {
        ix = 0; iei = 1; iea = 2; iW1 = 3; iW1e = 4;
        ia1s = 5; ia1d = 6; ia1e = 7; ib1 = 8;
        iW2 = 9; iW2e = 10; ia2s = 11; ia2d = 12; ia2e = 13; ib2 = 14;
    }
    const float* x   = (const float*)d_in[ix];
    const int*   ei  = (const int*)d_in[iei];
    const float* ea  = (const float*)d_in[iea];
    const float* W1  = (const float*)d_in[iW1];
    const float* W1e = (const float*)d_in[iW1e];
    const float* a1s = (const float*)d_in[ia1s];
    const float* a1d = (const float*)d_in[ia1d];
    const float* a1e = (const float*)d_in[ia1e];
    const float* b1  = (const float*)d_in[ib1];
    const float* W2  = (const float*)d_in[iW2];
    const float* W2e = (const float*)d_in[iW2e];
    const float* a2s = (const float*)d_in[ia2s];
    const float* a2d = (const float*)d_in[ia2d];
    const float* a2e = (const float*)d_in[ia2e];
    const float* b2  = (const float*)d_in[ib2];
    float* out = (float*)d_out;

    bool full = (out_size >= NN * 32 + 3 * EP);
    float* alphaOut = full ? out + (size_t)NN * 32 + 2 * (size_t)EP : nullptr;

    const int B = 256;
    kz<<<(NN * 4 + B - 1) / B, B>>>();
    k_outzero<<<(out_size + B - 1) / B, B>>>(out, out_size);
    k_prep<<<1, 128>>>(W1e, a1e, W2e, a2e);
    k_edge<<<(EE + B - 1) / B, B>>>(ei, ea);
    k_slscore<<<(NN * 4 + B - 1) / B, B>>>();
    k_scan1<<<NBLK, 1024>>>();
    k_scan2<<<1, 1>>>();
    k_scan3<<<(NN + 1 + B - 1) / B, B>>>();
    k_scatter<<<(EP + B - 1) / B, B>>>(ei);
    k_gemm1d<<<(NN * 128 + B - 1) / B, B>>>(x, W1);
    k_att1d<<<(NN * 4 + B - 1) / B, B>>>(a1s, a1d);
    k_walpha1<<<(NN * 4 * 32 + B - 1) / B, B>>>();           // warp per (node,head)
    k_wgather1<<<(NN * 32 + B - 1) / B, B>>>(b1);            // warp per node
    k_gemm2d<<<(NN * 32 + B - 1) / B, B>>>(W2);
    k_att2d<<<(NN + B - 1) / B, B>>>(a2s, a2d);
    k_walpha2<<<(NN * 32 + B - 1) / B, B>>>(alphaOut);       // warp per node
    k_wgather2<<<(NN * 32 + B - 1) / B, B>>>(b2, out);       // warp per node
    if (full) k_eidx<<<(2 * EP + B - 1) / B, B>>>(ei, out);
}

// round 13
// speedup vs baseline: 6.5785x; 1.7495x over previous
#include <cuda_runtime.h>

#define NN 100000
#define EE 1600000
#define EP (EE + NN)
#define NBLK ((NN + 1023) / 1024)   // 98
#define NEG 0.2f

// ---------------- scratch (static device globals; no allocation) ----------------
__device__ int   g_deg[NN];
__device__ int   g_cursor[NN];
__device__ int   g_offsets[NN + 1];
__device__ int   g_partials[NBLK + 2];
__device__ int   g_csrc[EP];                   // CSR: source node per slot
__device__ int   g_ceid[EP];                   // CSR: original edge id per slot
__device__ float g_h1[(size_t)NN * 128];
__device__ float g_als1[NN * 4];
__device__ float g_ald1[NN * 4];
__device__ float g_ale1[(size_t)EP * 4];       // per-ORIGINAL-edge layer-1 edge score
__device__ float g_alpha1[(size_t)EP * 4];     // per-CSR-slot softmax weight
__device__ float g_h1o[(size_t)NN * 128];
__device__ float g_h2l[(size_t)NN * 32];
__device__ float g_als2[NN];
__device__ float g_ald2[NN];
__device__ float g_ale2[EP];                   // per-ORIGINAL-edge layer-2 edge score
__device__ float g_alpha2[EP];                 // per-CSR-slot softmax weight
__device__ float g_v1[64];                     // folded W1e*a1e: [16 ed][4 h]
__device__ float g_v2[16];                     // folded W2e*a2e

__device__ __forceinline__ float lrelu(float x) { return x > 0.f ? x : NEG * x; }
__device__ __forceinline__ float elu(float x)   { return x > 0.f ? x : expm1f(x); }

// ---------------- init ----------------
__global__ void kz() {
    int i = blockIdx.x * blockDim.x + threadIdx.x;
    if (i < NN) { g_deg[i] = 0; g_cursor[i] = 0; }
}

__global__ void k_outzero(float* out, int n) {
    int i = blockIdx.x * blockDim.x + threadIdx.x;
    if (i < n) out[i] = 0.f;
}

// fold W_e with a_edge:  v1[ed][h] = sum_c W1e[ed, h*32+c] * a1e[h*32+c];  v2 likewise
__global__ void k_prep(const float* __restrict__ W1e, const float* __restrict__ a1e,
                       const float* __restrict__ W2e, const float* __restrict__ a2e) {
    int t = threadIdx.x;
    if (t < 64) {
        int ed = t >> 2, h = t & 3;
        float s = 0.f;
        for (int c = 0; c < 32; c++) s += W1e[ed * 128 + h * 32 + c] * a1e[h * 32 + c];
        g_v1[t] = s;
    } else if (t < 80) {
        int ed = t - 64;
        float s = 0.f;
        for (int c = 0; c < 32; c++) s += W2e[ed * 32 + c] * a2e[c];
        g_v2[ed] = s;
    }
}

// ---------------- per-edge folded scores + degree (1 atomic/edge) ----------------
__global__ void k_edge(const int* __restrict__ ei, const float* __restrict__ ea) {
    __shared__ float v1[64], v2[16];
    int t = threadIdx.x;
    if (t < 64) v1[t] = g_v1[t];
    if (t < 16) v2[t] = g_v2[t];
    __syncthreads();
    int e = blockIdx.x * blockDim.x + t;
    if (e >= EE) return;
    int d = ei[EE + e];
    atomicAdd(&g_deg[d], 1);
    float a[16];
    const float4* ep = (const float4*)(ea + (size_t)e * 16);
    float4 q0 = ep[0], q1 = ep[1], q2 = ep[2], q3 = ep[3];
    a[0]=q0.x;a[1]=q0.y;a[2]=q0.z;a[3]=q0.w; a[4]=q1.x;a[5]=q1.y;a[6]=q1.z;a[7]=q1.w;
    a[8]=q2.x;a[9]=q2.y;a[10]=q2.z;a[11]=q2.w; a[12]=q3.x;a[13]=q3.y;a[14]=q3.z;a[15]=q3.w;
    float s0=0,s1=0,s2=0,s3=0,u=0;
    #pragma unroll
    for (int k = 0; k < 16; k++) {
        float x = a[k];
        s0 += x * v1[k*4+0]; s1 += x * v1[k*4+1];
        s2 += x * v1[k*4+2]; s3 += x * v1[k*4+3];
        u  += x * v2[k];
    }
    size_t e4 = (size_t)e * 4;
    g_ale1[e4+0]=s0; g_ale1[e4+1]=s1; g_ale1[e4+2]=s2; g_ale1[e4+3]=s3;
    g_ale2[e] = u;
}

// ---------------- 3-kernel exclusive scan of counts = deg+1 ----------------
__global__ void k_scan1() {
    __shared__ int sh[1024];
    int tid = threadIdx.x;
    int i = blockIdx.x * 1024 + tid;
    int v = (i < NN) ? (g_deg[i] + 1) : 0;
    sh[tid] = v;
    __syncthreads();
    for (int off = 1; off < 1024; off <<= 1) {
        int t = 0;
        if (tid >= off) t = sh[tid - off];
        __syncthreads();
        sh[tid] += t;
        __syncthreads();
    }
    if (i < NN) g_offsets[i] = sh[tid] - v;
    if (tid == 1023) g_partials[blockIdx.x] = sh[1023];
}
__global__ void k_scan2() {
    int run = 0;
    for (int b = 0; b < NBLK; b++) { int t = g_partials[b]; g_partials[b] = run; run += t; }
    g_partials[NBLK] = run;
}
__global__ void k_scan3() {
    int i = blockIdx.x * blockDim.x + threadIdx.x;
    if (i > NN) return;
    if (i == NN) g_offsets[NN] = g_partials[NBLK];
    else g_offsets[i] += g_partials[i >> 10];
}

// ---------------- CSR scatter: src + eid ----------------
__global__ void k_scatter(const int* __restrict__ ei) {
    int t = blockIdx.x * blockDim.x + threadIdx.x;
    if (t >= EP) return;
    int s, d;
    if (t < EE) { s = ei[t]; d = ei[EE + t]; }
    else        { s = t - EE; d = s; }
    int pos = g_offsets[d] + atomicAdd(&g_cursor[d], 1);
    g_csrc[pos] = s;
    g_ceid[pos] = t;
}

// ---------------- self-loop scores = mean of incoming edge scores (warp per node) ----------------
__global__ void k_slsum() {
    int wid = (blockIdx.x * blockDim.x + threadIdx.x) >> 5;
    int lane = threadIdx.x & 31;
    if (wid >= NN) return;
    int st = g_offsets[wid], en = g_offsets[wid + 1];
    float s0 = 0.f, s1 = 0.f, s2 = 0.f, s3 = 0.f, u = 0.f;
    for (int i = st + lane; i < en; i += 32) {
        int eid = g_ceid[i];
        if (eid < EE) {
            const float4 a = *(const float4*)&g_ale1[(size_t)eid * 4];
            s0 += a.x; s1 += a.y; s2 += a.z; s3 += a.w;
            u += g_ale2[eid];
        }
    }
    #pragma unroll
    for (int o = 16; o; o >>= 1) {
        s0 += __shfl_xor_sync(~0u, s0, o);
        s1 += __shfl_xor_sync(~0u, s1, o);
        s2 += __shfl_xor_sync(~0u, s2, o);
        s3 += __shfl_xor_sync(~0u, s3, o);
        u  += __shfl_xor_sync(~0u, u, o);
    }
    if (lane == 0) {
        float inv = 1.f / fmaxf((float)(en - st - 1), 1.f);   // deg = slots - self-loop
        size_t b = (size_t)(EE + wid) * 4;
        g_ale1[b+0] = s0 * inv; g_ale1[b+1] = s1 * inv;
        g_ale1[b+2] = s2 * inv; g_ale1[b+3] = s3 * inv;
        g_ale2[EE + wid] = u * inv;
    }
}

// ---------------- GEMM1 (fresh tiled) + fused att1 dots ----------------
// block: 128 threads (thread = output column j), 32 rows per block. NN = 3125*32 exactly.
__global__ void k_gemm1t(const float* __restrict__ X, const float* __restrict__ W,
                         const float* __restrict__ a1s, const float* __restrict__ a1d) {
    __shared__ float xsT[128 * 36];          // [k][row], pad 36 for conflicts/alignment
    int tid = threadIdx.x;                   // column j = tid, head h = tid>>5
    int rowbase = blockIdx.x * 32;
    #pragma unroll 4
    for (int r = 0; r < 32; r++)
        xsT[tid * 36 + r] = X[(size_t)(rowbase + r) * 128 + tid];
    __syncthreads();
    float acc[32];
    #pragma unroll
    for (int r = 0; r < 32; r++) acc[r] = 0.f;
    for (int k = 0; k < 128; k++) {
        float wk = W[k * 128 + tid];
        const float4* xp = (const float4*)&xsT[k * 36];
        #pragma unroll
        for (int rr = 0; rr < 8; rr++) {
            float4 xv = xp[rr];
            acc[rr*4+0] += xv.x * wk;
            acc[rr*4+1] += xv.y * wk;
            acc[rr*4+2] += xv.z * wk;
            acc[rr*4+3] += xv.w * wk;
        }
    }
    #pragma unroll 4
    for (int r = 0; r < 32; r++)
        g_h1[(size_t)(rowbase + r) * 128 + tid] = acc[r];
    // fused attention dots: warp w owns head w's 32 columns
    float as = a1s[tid], ad = a1d[tid];      // a1s laid out [h][c] = [tid]
    int lane = tid & 31, h = tid >> 5;
    for (int r = 0; r < 32; r++) {
        float s = acc[r] * as, d = acc[r] * ad;
        #pragma unroll
        for (int o = 16; o; o >>= 1) {
            s += __shfl_xor_sync(~0u, s, o);
            d += __shfl_xor_sync(~0u, d, o);
        }
        if (lane == 0) {
            g_als1[(rowbase + r) * 4 + h] = s;
            g_ald1[(rowbase + r) * 4 + h] = d;
        }
    }
}

// ---------------- layer-1 softmax: warp per (node,head), 2-pass, no max ----------------
__global__ void k_walpha1() {
    int gw = (blockIdx.x * blockDim.x + threadIdx.x) >> 5;
    int lane = threadIdx.x & 31;
    if (gw >= NN * 4) return;
    int n = gw >> 2, h = gw & 3;
    int st = g_offsets[n], en = g_offsets[n + 1];
    float ald = g_ald1[n * 4 + h];
    float z = 0.f;
    for (int i = st + lane; i < en; i += 32) {
        int s = g_csrc[i], eid = g_ceid[i];
        float p = __expf(lrelu(g_als1[s * 4 + h] + ald + g_ale1[(size_t)eid * 4 + h]));
        g_alpha1[(size_t)i * 4 + h] = p;
        z += p;
    }
    #pragma unroll
    for (int o = 16; o; o >>= 1) z += __shfl_xor_sync(~0u, z, o);
    float invz = 1.f / z;
    for (int i = st + lane; i < en; i += 32)
        g_alpha1[(size_t)i * 4 + h] *= invz;     // same thread wrote these slots
}

// ---------------- layer-1 gather: warp per node ----------------
__global__ void k_wgather1(const float* __restrict__ b1) {
    int wid = (blockIdx.x * blockDim.x + threadIdx.x) >> 5;
    int lane = threadIdx.x & 31;
    if (wid >= NN) return;
    int st = g_offsets[wid], en = g_offsets[wid + 1];
    int h = lane >> 3;
    float4 acc = make_float4(0.f, 0.f, 0.f, 0.f);
    for (int i = st; i < en; i++) {
        int s = g_csrc[i];
        float a = g_alpha1[(size_t)i * 4 + h];
        float4 hv = *(const float4*)&g_h1[(size_t)s * 128 + lane * 4];
        acc.x += a * hv.x; acc.y += a * hv.y;
        acc.z += a * hv.z; acc.w += a * hv.w;
    }
    int j = lane * 4;
    float4 o;
    o.x = elu(acc.x + b1[j+0]); o.y = elu(acc.y + b1[j+1]);
    o.z = elu(acc.z + b1[j+2]); o.w = elu(acc.w + b1[j+3]);
    *(float4*)&g_h1o[(size_t)wid * 128 + j] = o;
}

// ---------------- GEMM2 (fresh tiled) + fused att2 dots ----------------
// block: 128 threads, 32 rows; thread (c = tid&31, g = tid>>5) does rows g*8..g*8+7, col c
__global__ void k_gemm2t(const float* __restrict__ W2,
                         const float* __restrict__ a2s, const float* __restrict__ a2d) {
    __shared__ float xsT[128 * 36];          // [k][row]
    int tid = threadIdx.x;
    int c = tid & 31, g = tid >> 5;
    int rowbase = blockIdx.x * 32;
    for (int i = tid; i < 32 * 128; i += 128) {
        int r = i >> 7, k = i & 127;
        xsT[k * 36 + r] = g_h1o[(size_t)(rowbase + r) * 128 + k];
    }
    __syncthreads();
    float acc[8];
    #pragma unroll
    for (int r = 0; r < 8; r++) acc[r] = 0.f;
    for (int k = 0; k < 128; k++) {
        float wk = W2[k * 32 + c];
        const float4* xp = (const float4*)&xsT[k * 36 + g * 8];
        float4 x0 = xp[0], x1 = xp[1];
        acc[0] += x0.x * wk; acc[1] += x0.y * wk;
        acc[2] += x0.z * wk; acc[3] += x0.w * wk;
        acc[4] += x1.x * wk; acc[5] += x1.y * wk;
        acc[6] += x1.z * wk; acc[7] += x1.w * wk;
    }
    #pragma unroll
    for (int r = 0; r < 8; r++)
        g_h2l[(size_t)(rowbase + g * 8 + r) * 32 + c] = acc[r];
    // fused attention dots (single head): warp reduce over cols
    float as = a2s[c], ad = a2d[c];
    #pragma unroll
    for (int r = 0; r < 8; r++) {
        float s = acc[r] * as, d = acc[r] * ad;
        #pragma unroll
        for (int o = 16; o; o >>= 1) {
            s += __shfl_xor_sync(~0u, s, o);
            d += __shfl_xor_sync(~0u, d, o);
        }
        if (c == 0) {
            g_als2[rowbase + g * 8 + r] = s;
            g_ald2[rowbase + g * 8 + r] = d;
        }
    }
}

// ---------------- layer-2 softmax: warp per node, 2-pass, no max ----------------
__global__ void k_walpha2(float* __restrict__ outAlpha) {
    int wid = (blockIdx.x * blockDim.x + threadIdx.x) >> 5;
    int lane = threadIdx.x & 31;
    if (wid >= NN) return;
    int st = g_offsets[wid], en = g_offsets[wid + 1];
    float ald = g_ald2[wid];
    float z = 0.f;
    for (int i = st + lane; i < en; i += 32) {
        int s = g_csrc[i], eid = g_ceid[i];
        float p = __expf(lrelu(g_als2[s] + ald + g_ale2[eid]));
        g_alpha2[i] = p;
        z += p;
    }
    #pragma unroll
    for (int o = 16; o; o >>= 1) z += __shfl_xor_sync(~0u, z, o);
    float invz = 1.f / z;
    for (int i = st + lane; i < en; i += 32) {
        float a = g_alpha2[i] * invz;
        g_alpha2[i] = a;
        if (outAlpha) outAlpha[g_ceid[i]] = a;
    }
}

// ---------------- layer-2 gather: warp per node (lane = channel) ----------------
__global__ void k_wgather2(const float* __restrict__ b2, float* __restrict__ outH2) {
    int wid = (blockIdx.x * blockDim.x + threadIdx.x) >> 5;
    int lane = threadIdx.x & 31;
    if (wid >= NN) return;
    int st = g_offsets[wid], en = g_offsets[wid + 1];
    float acc = 0.f;
    for (int i = st; i < en; i++) {
        int s = g_csrc[i];
        acc += g_alpha2[i] * g_h2l[(size_t)s * 32 + lane];
    }
    outH2[wid * 32 + lane] = elu(acc + b2[lane]);
}

// ---------------- edge_index_sl output (as float) ----------------
__global__ void k_eidx(const int* __restrict__ ei, float* __restrict__ out) {
    int t = blockIdx.x * blockDim.x + threadIdx.x;
    if (t >= 2 * EP) return;
    int row = t / EP, j = t - row * EP;
    int v = (j < EE) ? ei[row * EE + j] : (j - EE);
    out[(size_t)NN * 32 + t] = (float)v;
}

// ---------------- launch ----------------
extern "C" void kernel_launch(void* const* d_in, const int* in_sizes, int n_in,
                              void* d_out, int out_size) {
    int ix, iei, iea, iW1, iW1e, ia1s, ia1d, ia1e, ib1, iW2, iW2e, ia2s, ia2d, ia2e, ib2;
    if (n_in >= 15 && in_sizes[0] == 16384) {
        iW1 = 0; iW1e = 1; iW2 = 2; iW2e = 3;
        ia1d = 4; ia1e = 5; ia1s = 6;
        ia2d = 7; ia2e = 8; ia2s = 9;
        ib1 = 10; ib2 = 11; iea = 12; iei = 13; ix = 14;
    } else {
        ix = 0; iei = 1; iea = 2; iW1 = 3; iW1e = 4;
        ia1s = 5; ia1d = 6; ia1e = 7; ib1 = 8;
        iW2 = 9; iW2e = 10; ia2s = 11; ia2d = 12; ia2e = 13; ib2 = 14;
    }
    const float* x   = (const float*)d_in[ix];
    const int*   ei  = (const int*)d_in[iei];
    const float* ea  = (const float*)d_in[iea];
    const float* W1  = (const float*)d_in[iW1];
    const float* a1s = (const float*)d_in[ia1s];
    const float* a1d = (const float*)d_in[ia1d];
    const float* b1  = (const float*)d_in[ib1];
    const float* W2  = (const float*)d_in[iW2];
    const float* a2s = (const float*)d_in[ia2s];
    const float* a2d = (const float*)d_in[ia2d];
    const float* b2  = (const float*)d_in[ib2];
    const float* W1e = (const float*)d_in[iW1e];
    const float* a1e = (const float*)d_in[ia1e];
    const float* W2e = (const float*)d_in[iW2e];
    const float* a2e = (const float*)d_in[ia2e];
    float* out = (float*)d_out;

    bool full = (out_size >= NN * 32 + 3 * EP);
    float* alphaOut = full ? out + (size_t)NN * 32 + 2 * (size_t)EP : nullptr;

    const int B = 256;
    kz<<<(NN + B - 1) / B, B>>>();
    k_outzero<<<(out_size + B - 1) / B, B>>>(out, out_size);
    k_prep<<<1, 128>>>(W1e, a1e, W2e, a2e);
    k_edge<<<(EE + B - 1) / B, B>>>(ei, ea);
    k_scan1<<<NBLK, 1024>>>();
    k_scan2<<<1, 1>>>();
    k_scan3<<<(NN + 1 + B - 1) / B, B>>>();
    k_scatter<<<(EP + B - 1) / B, B>>>(ei);
    k_slsum<<<(NN * 32 + B - 1) / B, B>>>();                 // warp per node
    k_gemm1t<<<NN / 32, 128>>>(x, W1, a1s, a1d);             // 3125 blocks
    k_walpha1<<<(NN * 4 * 32 + B - 1) / B, B>>>();           // warp per (node,head)
    k_wgather1<<<(NN * 32 + B - 1) / B, B>>>(b1);            // warp per node
    k_gemm2t<<<NN / 32, 128>>>(W2, a2s, a2d);                // 3125 blocks
    k_walpha2<<<(NN * 32 + B - 1) / B, B>>>(alphaOut);       // warp per node
    k_wgather2<<<(NN * 32 + B - 1) / B, B>>>(b2, out);       // warp per node
    if (full) k_eidx<<<(2 * EP + B - 1) / B, B>>>(ei, out);
}

// round 14
// speedup vs baseline: 7.7228x; 1.1739x over previous
#include <cuda_runtime.h>

#define NN 100000
#define EE 1600000
#define EP (EE + NN)
#define NBLK ((NN + 1023) / 1024)   // 98
#define NEG 0.2f

// ---------------- scratch (static device globals; no allocation) ----------------
__device__ int    g_deg[NN];
__device__ int    g_cursor[NN];
__device__ int    g_offsets[NN + 1];
__device__ int    g_partials[NBLK + 2];
__device__ int    g_csrc[EP];                  // CSR: source node per slot
__device__ int    g_ceid[EP];                  // CSR: original edge id per slot
__device__ float  g_ale1[(size_t)EE * 4];      // per-original-edge layer-1 scores
__device__ float  g_ale2[EE];                  // per-original-edge layer-2 scores
__device__ float4 g_cal1[EP];                  // CSR-ordered layer-1 scores
__device__ float  g_cal2[EP];                  // CSR-ordered layer-2 scores
__device__ float4 g_alpha1[EP];                // CSR-ordered layer-1 softmax weights
__device__ float  g_alpha2[EP];                // CSR-ordered layer-2 softmax weights
__device__ float  g_h1[(size_t)NN * 128];
__device__ float  g_als1[NN * 4];
__device__ float  g_ald1[NN * 4];
__device__ float  g_h1o[(size_t)NN * 128];
__device__ float  g_h2l[(size_t)NN * 32];
__device__ float  g_als2[NN];
__device__ float  g_ald2[NN];
__device__ float  g_v1[64];                    // folded W1e*a1e: [16 ed][4 h]
__device__ float  g_v2[16];                    // folded W2e*a2e

__device__ __forceinline__ float lrelu(float x) { return x > 0.f ? x : NEG * x; }
__device__ __forceinline__ float elu(float x)   { return x > 0.f ? x : expm1f(x); }

// packed f32x2 helpers (Blackwell; PTX-only form)
__device__ __forceinline__ unsigned long long pack2(float lo, float hi) {
    unsigned long long r;
    asm("mov.b64 %0, {%1, %2};" : "=l"(r) : "r"(__float_as_uint(lo)), "r"(__float_as_uint(hi)));
    return r;
}
__device__ __forceinline__ void unpack2(unsigned long long v, float& lo, float& hi) {
    unsigned int a, b;
    asm("mov.b64 {%0, %1}, %2;" : "=r"(a), "=r"(b) : "l"(v));
    lo = __uint_as_float(a); hi = __uint_as_float(b);
}
__device__ __forceinline__ void ffma2(unsigned long long& d, unsigned long long a, unsigned long long b) {
    asm("fma.rn.f32x2 %0, %1, %2, %3;" : "=l"(d) : "l"(a), "l"(b), "l"(d));
}

// ---------------- init ----------------
__global__ void kz() {
    int i = blockIdx.x * blockDim.x + threadIdx.x;
    if (i < NN) { g_deg[i] = 0; g_cursor[i] = 0; }
}

// fold W_e with a_edge
__global__ void k_prep(const float* __restrict__ W1e, const float* __restrict__ a1e,
                       const float* __restrict__ W2e, const float* __restrict__ a2e) {
    int t = threadIdx.x;
    if (t < 64) {
        int ed = t >> 2, h = t & 3;
        float s = 0.f;
        for (int c = 0; c < 32; c++) s += W1e[ed * 128 + h * 32 + c] * a1e[h * 32 + c];
        g_v1[t] = s;
    } else if (t < 80) {
        int ed = t - 64;
        float s = 0.f;
        for (int c = 0; c < 32; c++) s += W2e[ed * 32 + c] * a2e[c];
        g_v2[ed] = s;
    }
}

// ---------------- per-edge folded scores + degree (1 atomic/edge) ----------------
__global__ void k_edge(const int* __restrict__ ei, const float* __restrict__ ea) {
    __shared__ float v1[64], v2[16];
    int t = threadIdx.x;
    if (t < 64) v1[t] = g_v1[t];
    if (t < 16) v2[t] = g_v2[t];
    __syncthreads();
    int e = blockIdx.x * blockDim.x + t;
    if (e >= EE) return;
    int d = ei[EE + e];
    atomicAdd(&g_deg[d], 1);
    float a[16];
    const float4* ep = (const float4*)(ea + (size_t)e * 16);
    float4 q0 = ep[0], q1 = ep[1], q2 = ep[2], q3 = ep[3];
    a[0]=q0.x;a[1]=q0.y;a[2]=q0.z;a[3]=q0.w; a[4]=q1.x;a[5]=q1.y;a[6]=q1.z;a[7]=q1.w;
    a[8]=q2.x;a[9]=q2.y;a[10]=q2.z;a[11]=q2.w; a[12]=q3.x;a[13]=q3.y;a[14]=q3.z;a[15]=q3.w;
    float s0=0,s1=0,s2=0,s3=0,u=0;
    #pragma unroll
    for (int k = 0; k < 16; k++) {
        float x = a[k];
        s0 += x * v1[k*4+0]; s1 += x * v1[k*4+1];
        s2 += x * v1[k*4+2]; s3 += x * v1[k*4+3];
        u  += x * v2[k];
    }
    size_t e4 = (size_t)e * 4;
    g_ale1[e4+0]=s0; g_ale1[e4+1]=s1; g_ale1[e4+2]=s2; g_ale1[e4+3]=s3;
    g_ale2[e] = u;
}

// ---------------- 3-kernel exclusive scan of counts = deg+1 ----------------
__global__ void k_scan1() {
    __shared__ int sh[1024];
    int tid = threadIdx.x;
    int i = blockIdx.x * 1024 + tid;
    int v = (i < NN) ? (g_deg[i] + 1) : 0;
    sh[tid] = v;
    __syncthreads();
    for (int off = 1; off < 1024; off <<= 1) {
        int t = 0;
        if (tid >= off) t = sh[tid - off];
        __syncthreads();
        sh[tid] += t;
        __syncthreads();
    }
    if (i < NN) g_offsets[i] = sh[tid] - v;
    if (tid == 1023) g_partials[blockIdx.x] = sh[1023];
}
__global__ void k_scan2() {
    int run = 0;
    for (int b = 0; b < NBLK; b++) { int t = g_partials[b]; g_partials[b] = run; run += t; }
    g_partials[NBLK] = run;
}
__global__ void k_scan3() {
    int i = blockIdx.x * blockDim.x + threadIdx.x;
    if (i > NN) return;
    if (i == NN) g_offsets[NN] = g_partials[NBLK];
    else g_offsets[i] += g_partials[i >> 10];
}

// ---------------- CSR scatter: src + eid + CSR-ordered scores ----------------
__global__ void k_scatter(const int* __restrict__ ei) {
    int t = blockIdx.x * blockDim.x + threadIdx.x;
    if (t >= EP) return;
    int s, d;
    if (t < EE) { s = ei[t]; d = ei[EE + t]; }
    else        { s = t - EE; d = s; }
    int pos = g_offsets[d] + atomicAdd(&g_cursor[d], 1);
    g_csrc[pos] = s;
    g_ceid[pos] = t;
    if (t < EE) {   // self-loop slots are filled by k_slsum
        g_cal1[pos] = *(const float4*)&g_ale1[(size_t)t * 4];
        g_cal2[pos] = g_ale2[t];
    }
}

// ---------------- self-loop scores = mean of incoming edge scores (warp per node) ----------------
__global__ void k_slsum() {
    int wid = (blockIdx.x * blockDim.x + threadIdx.x) >> 5;
    int lane = threadIdx.x & 31;
    if (wid >= NN) return;
    int st = g_offsets[wid], en = g_offsets[wid + 1];
    float s0 = 0.f, s1 = 0.f, s2 = 0.f, s3 = 0.f, u = 0.f;
    int selfpos = -1;
    for (int i = st + lane; i < en; i += 32) {
        if (g_ceid[i] < EE) {
            float4 a = g_cal1[i];
            s0 += a.x; s1 += a.y; s2 += a.z; s3 += a.w;
            u += g_cal2[i];
        } else selfpos = i;
    }
    #pragma unroll
    for (int o = 16; o; o >>= 1) {
        s0 += __shfl_xor_sync(~0u, s0, o);
        s1 += __shfl_xor_sync(~0u, s1, o);
        s2 += __shfl_xor_sync(~0u, s2, o);
        s3 += __shfl_xor_sync(~0u, s3, o);
        u  += __shfl_xor_sync(~0u, u, o);
        selfpos = max(selfpos, __shfl_xor_sync(~0u, selfpos, o));
    }
    if (lane == 0) {
        float inv = 1.f / fmaxf((float)(en - st - 1), 1.f);
        g_cal1[selfpos] = make_float4(s0 * inv, s1 * inv, s2 * inv, s3 * inv);
        g_cal2[selfpos] = u * inv;
    }
}

// ---------------- GEMM1 (f32x2 packed) + fused att1 dots ----------------
// 128 threads (thread = output column), 32 rows per block. NN = 3125*32.
__global__ void k_gemm1t(const float* __restrict__ X, const float* __restrict__ W,
                         const float* __restrict__ a1s, const float* __restrict__ a1d) {
    __shared__ float xsT[128 * 36];          // [k][row], pad 36
    int tid = threadIdx.x;
    int rowbase = blockIdx.x * 32;
    #pragma unroll 4
    for (int r = 0; r < 32; r++)
        xsT[tid * 36 + r] = X[(size_t)(rowbase + r) * 128 + tid];
    __syncthreads();
    unsigned long long acc2[16];
    #pragma unroll
    for (int p = 0; p < 16; p++) acc2[p] = 0ull;
    for (int k = 0; k < 128; k++) {
        float wk = W[k * 128 + tid];
        unsigned long long wk2 = pack2(wk, wk);
        const double2* xp = (const double2*)&xsT[k * 36];   // 144B-aligned
        #pragma unroll
        for (int rr = 0; rr < 4; rr++) {
            double2 xv = xp[rr];        // rows 4rr..4rr+3 packed as 2 f32x2
            ffma2(acc2[rr*4+0], __double_as_longlong(xv.x), wk2);
            ffma2(acc2[rr*4+1], __double_as_longlong(xv.y), wk2);
            double2 xw = xp[rr + 4];    // rows 16+4rr..16+4rr+3
            ffma2(acc2[rr*4+2], __double_as_longlong(xw.x), wk2);
            ffma2(acc2[rr*4+3], __double_as_longlong(xw.y), wk2);
        }
    }
    // acc2[rr*4+q]: q=0 rows(4rr,4rr+1); q=1 rows(4rr+2,4rr+3); q=2 rows(16+4rr,16+4rr+1); q=3 rows(16+4rr+2,+3)
    float as = a1s[tid], ad = a1d[tid];
    int lane = tid & 31, h = tid >> 5;
    #pragma unroll
    for (int rr = 0; rr < 4; rr++) {
        #pragma unroll
        for (int q = 0; q < 4; q++) {
            int r0 = (q >> 1) * 16 + rr * 4 + (q & 1) * 2;  // first of the row pair
            float lo, hi; unpack2(acc2[rr*4+q], lo, hi);
            g_h1[(size_t)(rowbase + r0) * 128 + tid] = lo;
            g_h1[(size_t)(rowbase + r0 + 1) * 128 + tid] = hi;
            float sl = lo * as, dl = lo * ad, sh = hi * as, dh = hi * ad;
            #pragma unroll
            for (int o = 16; o; o >>= 1) {
                sl += __shfl_xor_sync(~0u, sl, o);
                dl += __shfl_xor_sync(~0u, dl, o);
                sh += __shfl_xor_sync(~0u, sh, o);
                dh += __shfl_xor_sync(~0u, dh, o);
            }
            if (lane == 0) {
                g_als1[(rowbase + r0) * 4 + h] = sl;
                g_ald1[(rowbase + r0) * 4 + h] = dl;
                g_als1[(rowbase + r0 + 1) * 4 + h] = sh;
                g_ald1[(rowbase + r0 + 1) * 4 + h] = dh;
            }
        }
    }
}

// ---------------- layer-1 softmax: warp per node, ALL 4 heads, 2-pass ----------------
__global__ void k_walpha1() {
    int wid = (blockIdx.x * blockDim.x + threadIdx.x) >> 5;
    int lane = threadIdx.x & 31;
    if (wid >= NN) return;
    int st = g_offsets[wid], en = g_offsets[wid + 1];
    float4 ald = *(const float4*)&g_ald1[wid * 4];
    float z0 = 0.f, z1 = 0.f, z2 = 0.f, z3 = 0.f;
    for (int i = st + lane; i < en; i += 32) {
        int s = g_csrc[i];
        float4 als = *(const float4*)&g_als1[s * 4];
        float4 ae = g_cal1[i];
        float p0 = __expf(lrelu(als.x + ald.x + ae.x));
        float p1 = __expf(lrelu(als.y + ald.y + ae.y));
        float p2 = __expf(lrelu(als.z + ald.z + ae.z));
        float p3 = __expf(lrelu(als.w + ald.w + ae.w));
        g_alpha1[i] = make_float4(p0, p1, p2, p3);
        z0 += p0; z1 += p1; z2 += p2; z3 += p3;
    }
    #pragma unroll
    for (int o = 16; o; o >>= 1) {
        z0 += __shfl_xor_sync(~0u, z0, o);
        z1 += __shfl_xor_sync(~0u, z1, o);
        z2 += __shfl_xor_sync(~0u, z2, o);
        z3 += __shfl_xor_sync(~0u, z3, o);
    }
    float i0 = 1.f / z0, i1 = 1.f / z1, i2 = 1.f / z2, i3 = 1.f / z3;
    for (int i = st + lane; i < en; i += 32) {
        float4 p = g_alpha1[i];
        g_alpha1[i] = make_float4(p.x * i0, p.y * i1, p.z * i2, p.w * i3);
    }
}

// ---------------- layer-1 gather: warp per node ----------------
__global__ void k_wgather1(const float* __restrict__ b1) {
    int wid = (blockIdx.x * blockDim.x + threadIdx.x) >> 5;
    int lane = threadIdx.x & 31;
    if (wid >= NN) return;
    int st = g_offsets[wid], en = g_offsets[wid + 1];
    int h = lane >> 3;
    float4 acc = make_float4(0.f, 0.f, 0.f, 0.f);
    for (int i = st; i < en; i++) {
        int s = g_csrc[i];
        float a = ((const float*)&g_alpha1[i])[h];
        float4 hv = *(const float4*)&g_h1[(size_t)s * 128 + lane * 4];
        acc.x += a * hv.x; acc.y += a * hv.y;
        acc.z += a * hv.z; acc.w += a * hv.w;
    }
    int j = lane * 4;
    float4 o;
    o.x = elu(acc.x + b1[j+0]); o.y = elu(acc.y + b1[j+1]);
    o.z = elu(acc.z + b1[j+2]); o.w = elu(acc.w + b1[j+3]);
    *(float4*)&g_h1o[(size_t)wid * 128 + j] = o;
}

// ---------------- GEMM2 (f32x2 packed) + fused att2 dots ----------------
__global__ void k_gemm2t(const float* __restrict__ W2,
                         const float* __restrict__ a2s, const float* __restrict__ a2d) {
    __shared__ float xsT[128 * 36];
    int tid = threadIdx.x;
    int c = tid & 31, g = tid >> 5;
    int rowbase = blockIdx.x * 32;
    for (int i = tid; i < 32 * 128; i += 128) {
        int r = i >> 7, k = i & 127;
        xsT[k * 36 + r] = g_h1o[(size_t)(rowbase + r) * 128 + k];
    }
    __syncthreads();
    unsigned long long acc2[4];
    #pragma unroll
    for (int p = 0; p < 4; p++) acc2[p] = 0ull;
    for (int k = 0; k < 128; k++) {
        float wk = W2[k * 32 + c];
        unsigned long long wk2 = pack2(wk, wk);
        const double2* xp = (const double2*)&xsT[k * 36 + g * 8];
        double2 x0 = xp[0], x1 = xp[1];
        ffma2(acc2[0], __double_as_longlong(x0.x), wk2);
        ffma2(acc2[1], __double_as_longlong(x0.y), wk2);
        ffma2(acc2[2], __double_as_longlong(x1.x), wk2);
        ffma2(acc2[3], __double_as_longlong(x1.y), wk2);
    }
    float as = a2s[c], ad = a2d[c];
    #pragma unroll
    for (int p = 0; p < 4; p++) {
        float lo, hi; unpack2(acc2[p], lo, hi);
        int r0 = rowbase + g * 8 + p * 2;
        g_h2l[(size_t)r0 * 32 + c] = lo;
        g_h2l[(size_t)(r0 + 1) * 32 + c] = hi;
        float sl = lo * as, dl = lo * ad, sh = hi * as, dh = hi * ad;
        #pragma unroll
        for (int o = 16; o; o >>= 1) {
            sl += __shfl_xor_sync(~0u, sl, o);
            dl += __shfl_xor_sync(~0u, dl, o);
            sh += __shfl_xor_sync(~0u, sh, o);
            dh += __shfl_xor_sync(~0u, dh, o);
        }
        if (c == 0) {
            g_als2[r0] = sl; g_ald2[r0] = dl;
            g_als2[r0 + 1] = sh; g_ald2[r0 + 1] = dh;
        }
    }
}

// ---------------- layer-2 softmax: warp per node, 2-pass ----------------
__global__ void k_walpha2(float* __restrict__ outAlpha) {
    int wid = (blockIdx.x * blockDim.x + threadIdx.x) >> 5;
    int lane = threadIdx.x & 31;
    if (wid >= NN) return;
    int st = g_offsets[wid], en = g_offsets[wid + 1];
    float ald = g_ald2[wid];
    float z = 0.f;
    for (int i = st + lane; i < en; i += 32) {
        int s = g_csrc[i];
        float p = __expf(lrelu(g_als2[s] + ald + g_cal2[i]));
        g_alpha2[i] = p;
        z += p;
    }
    #pragma unroll
    for (int o = 16; o; o >>= 1) z += __shfl_xor_sync(~0u, z, o);
    float invz = 1.f / z;
    for (int i = st + lane; i < en; i += 32) {
        float a = g_alpha2[i] * invz;
        g_alpha2[i] = a;
        if (outAlpha) outAlpha[g_ceid[i]] = a;
    }
}

// ---------------- layer-2 gather: warp per node (lane = channel) ----------------
__global__ void k_wgather2(const float* __restrict__ b2, float* __restrict__ outH2) {
    int wid = (blockIdx.x * blockDim.x + threadIdx.x) >> 5;
    int lane = threadIdx.x & 31;
    if (wid >= NN) return;
    int st = g_offsets[wid], en = g_offsets[wid + 1];
    float acc = 0.f;
    for (int i = st; i < en; i++) {
        int s = g_csrc[i];
        acc += g_alpha2[i] * g_h2l[(size_t)s * 32 + lane];
    }
    outH2[wid * 32 + lane] = elu(acc + b2[lane]);
}

// ---------------- edge_index_sl output (as float) ----------------
__global__ void k_eidx(const int* __restrict__ ei, float* __restrict__ out) {
    int t = blockIdx.x * blockDim.x + threadIdx.x;
    if (t >= 2 * EP) return;
    int row = t / EP, j = t - row * EP;
    int v = (j < EE) ? ei[row * EE + j] : (j - EE);
    out[(size_t)NN * 32 + t] = (float)v;
}

// ---------------- launch ----------------
extern "C" void kernel_launch(void* const* d_in, const int* in_sizes, int n_in,
                              void* d_out, int out_size) {
    int ix, iei, iea, iW1, iW1e, ia1s, ia1d, ia1e, ib1, iW2, iW2e, ia2s, ia2d, ia2e, ib2;
    if (n_in >= 15 && in_sizes[0] == 16384) {
        iW1 = 0; iW1e = 1; iW2 = 2; iW2e = 3;
        ia1d = 4; ia1e = 5; ia1s = 6;
        ia2d = 7; ia2e = 8; ia2s = 9;
        ib1 = 10; ib2 = 11; iea = 12; iei = 13; ix = 14;
    } else {
        ix = 0; iei = 1; iea = 2; iW1 = 3; iW1e = 4;
        ia1s = 5; ia1d = 6; ia1e = 7; ib1 = 8;
        iW2 = 9; iW2e = 10; ia2s = 11; ia2d = 12; ia2e = 13; ib2 = 14;
    }
    const float* x   = (const float*)d_in[ix];
    const int*   ei  = (const int*)d_in[iei];
    const float* ea  = (const float*)d_in[iea];
    const float* W1  = (const float*)d_in[iW1];
    const float* a1s = (const float*)d_in[ia1s];
    const float* a1d = (const float*)d_in[ia1d];
    const float* b1  = (const float*)d_in[ib1];
    const float* W2  = (const float*)d_in[iW2];
    const float* a2s = (const float*)d_in[ia2s];
    const float* a2d = (const float*)d_in[ia2d];
    const float* b2  = (const float*)d_in[ib2];
    const float* W1e = (const float*)d_in[iW1e];
    const float* a1e = (const float*)d_in[ia1e];
    const float* W2e = (const float*)d_in[iW2e];
    const float* a2e = (const float*)d_in[ia2e];
    float* out = (float*)d_out;

    bool full = (out_size >= NN * 32 + 3 * EP);
    float* alphaOut = full ? out + (size_t)NN * 32 + 2 * (size_t)EP : nullptr;

    const int B = 256;
    kz<<<(NN + B - 1) / B, B>>>();
    k_prep<<<1, 128>>>(W1e, a1e, W2e, a2e);
    k_edge<<<(EE + B - 1) / B, B>>>(ei, ea);
    k_scan1<<<NBLK, 1024>>>();
    k_scan2<<<1, 1>>>();
    k_scan3<<<(NN + 1 + B - 1) / B, B>>>();
    k_scatter<<<(EP + B - 1) / B, B>>>(ei);
    k_slsum<<<(NN * 32 + B - 1) / B, B>>>();                 // warp per node
    k_gemm1t<<<NN / 32, 128>>>(x, W1, a1s, a1d);
    k_walpha1<<<(NN * 32 + B - 1) / B, B>>>();               // warp per node (all heads)
    k_wgather1<<<(NN * 32 + B - 1) / B, B>>>(b1);            // warp per node
    k_gemm2t<<<NN / 32, 128>>>(W2, a2s, a2d);
    k_walpha2<<<(NN * 32 + B - 1) / B, B>>>(alphaOut);       // warp per node
    k_wgather2<<<(NN * 32 + B - 1) / B, B>>>(b2, out);       // warp per node
    if (full) k_eidx<<<(2 * EP + B - 1) / B, B>>>(ei, out);
}

// round 15
// speedup vs baseline: 8.2265x; 1.0652x over previous
#include <cuda_runtime.h>

#define NN 100000
#define EE 1600000
#define EP (EE + NN)
#define NBLK ((NN + 1023) / 1024)   // 98
#define NEG 0.2f

// ---------------- scratch (static device globals; no allocation) ----------------
__device__ int    g_deg[NN];
__device__ int    g_cursor[NN];
__device__ int    g_offsets[NN + 1];
__device__ int    g_partials[NBLK + 2];
__device__ int    g_csrc[EP];                  // CSR: source node per slot
__device__ int    g_ceid[EP];                  // CSR: original edge id per slot
__device__ float  g_ale1[(size_t)EE * 4];      // per-original-edge layer-1 scores
__device__ float  g_ale2[EE];                  // per-original-edge layer-2 scores
__device__ float4 g_cal1[EP];                  // CSR-ordered layer-1 scores (real edges)
__device__ float  g_cal2[EP];                  // CSR-ordered layer-2 scores (real edges)
__device__ float4 g_alpha1[EP];                // CSR-ordered layer-1 numerators
__device__ float  g_alpha2[EP];                // CSR-ordered layer-2 numerators
__device__ float  g_h1[(size_t)NN * 128];
__device__ float  g_als1[NN * 4];
__device__ float  g_ald1[NN * 4];
__device__ float  g_h1o[(size_t)NN * 128];
__device__ float  g_h2l[(size_t)NN * 32];
__device__ float  g_als2[NN];
__device__ float  g_ald2[NN];
__device__ float  g_v1[64];                    // folded W1e*a1e: [16 ed][4 h]
__device__ float  g_v2[16];                    // folded W2e*a2e

__device__ __forceinline__ float lrelu(float x) { return x > 0.f ? x : NEG * x; }
__device__ __forceinline__ float elu(float x)   { return x > 0.f ? x : expm1f(x); }

// packed f32x2 helpers (Blackwell; PTX-only form)
__device__ __forceinline__ unsigned long long pack2(float lo, float hi) {
    unsigned long long r;
    asm("mov.b64 %0, {%1, %2};" : "=l"(r) : "r"(__float_as_uint(lo)), "r"(__float_as_uint(hi)));
    return r;
}
__device__ __forceinline__ void unpack2(unsigned long long v, float& lo, float& hi) {
    unsigned int a, b;
    asm("mov.b64 {%0, %1}, %2;" : "=r"(a), "=r"(b) : "l"(v));
    lo = __uint_as_float(a); hi = __uint_as_float(b);
}
__device__ __forceinline__ void ffma2(unsigned long long& d, unsigned long long a, unsigned long long b) {
    asm("fma.rn.f32x2 %0, %1, %2, %3;" : "=l"(d) : "l"(a), "l"(b), "l"(d));
}

// ---------------- init ----------------
__global__ void kz() {
    int i = blockIdx.x * blockDim.x + threadIdx.x;
    if (i < NN) { g_deg[i] = 0; g_cursor[i] = 0; }
}

// fold W_e with a_edge
__global__ void k_prep(const float* __restrict__ W1e, const float* __restrict__ a1e,
                       const float* __restrict__ W2e, const float* __restrict__ a2e) {
    int t = threadIdx.x;
    if (t < 64) {
        int ed = t >> 2, h = t & 3;
        float s = 0.f;
        for (int c = 0; c < 32; c++) s += W1e[ed * 128 + h * 32 + c] * a1e[h * 32 + c];
        g_v1[t] = s;
    } else if (t < 80) {
        int ed = t - 64;
        float s = 0.f;
        for (int c = 0; c < 32; c++) s += W2e[ed * 32 + c] * a2e[c];
        g_v2[ed] = s;
    }
}

// ---------------- per-edge folded scores + degree; 2 edges/thread for MLP ----------------
__global__ void k_edge(const int* __restrict__ ei, const float* __restrict__ ea) {
    __shared__ float v1[64], v2[16];
    int t = threadIdx.x;
    if (t < 64) v1[t] = g_v1[t];
    if (t < 16) v2[t] = g_v2[t];
    __syncthreads();
    int base = blockIdx.x * 512 + t;           // EE = 3125 * 512 exactly
    #pragma unroll
    for (int half = 0; half < 2; half++) {
        int e = base + half * 256;
        int d = ei[EE + e];
        atomicAdd(&g_deg[d], 1);
        float a[16];
        const float4* ep = (const float4*)(ea + (size_t)e * 16);
        float4 q0 = ep[0], q1 = ep[1], q2 = ep[2], q3 = ep[3];
        a[0]=q0.x;a[1]=q0.y;a[2]=q0.z;a[3]=q0.w; a[4]=q1.x;a[5]=q1.y;a[6]=q1.z;a[7]=q1.w;
        a[8]=q2.x;a[9]=q2.y;a[10]=q2.z;a[11]=q2.w; a[12]=q3.x;a[13]=q3.y;a[14]=q3.z;a[15]=q3.w;
        float s0=0,s1=0,s2=0,s3=0,u=0;
        #pragma unroll
        for (int k = 0; k < 16; k++) {
            float x = a[k];
            s0 += x * v1[k*4+0]; s1 += x * v1[k*4+1];
            s2 += x * v1[k*4+2]; s3 += x * v1[k*4+3];
            u  += x * v2[k];
        }
        size_t e4 = (size_t)e * 4;
        g_ale1[e4+0]=s0; g_ale1[e4+1]=s1; g_ale1[e4+2]=s2; g_ale1[e4+3]=s3;
        g_ale2[e] = u;
    }
}

// ---------------- 3-kernel exclusive scan of counts = deg+1 ----------------
__global__ void k_scan1() {
    __shared__ int sh[1024];
    int tid = threadIdx.x;
    int i = blockIdx.x * 1024 + tid;
    int v = (i < NN) ? (g_deg[i] + 1) : 0;
    sh[tid] = v;
    __syncthreads();
    for (int off = 1; off < 1024; off <<= 1) {
        int t = 0;
        if (tid >= off) t = sh[tid - off];
        __syncthreads();
        sh[tid] += t;
        __syncthreads();
    }
    if (i < NN) g_offsets[i] = sh[tid] - v;
    if (tid == 1023) g_partials[blockIdx.x] = sh[1023];
}
__global__ void k_scan2() {
    int run = 0;
    for (int b = 0; b < NBLK; b++) { int t = g_partials[b]; g_partials[b] = run; run += t; }
    g_partials[NBLK] = run;
}
__global__ void k_scan3() {
    int i = blockIdx.x * blockDim.x + threadIdx.x;
    if (i > NN) return;
    if (i == NN) g_offsets[NN] = g_partials[NBLK];
    else g_offsets[i] += g_partials[i >> 10];
}

// ---------------- CSR scatter: src + eid + CSR-ordered scores ----------------
__global__ void k_scatter(const int* __restrict__ ei) {
    int t = blockIdx.x * blockDim.x + threadIdx.x;
    if (t >= EP) return;
    int s, d;
    if (t < EE) { s = ei[t]; d = ei[EE + t]; }
    else        { s = t - EE; d = s; }
    int pos = g_offsets[d] + atomicAdd(&g_cursor[d], 1);
    g_csrc[pos] = s;
    g_ceid[pos] = t;
    if (t < EE) {   // self-loop slot scores live in registers inside the agg kernels
        g_cal1[pos] = *(const float4*)&g_ale1[(size_t)t * 4];
        g_cal2[pos] = g_ale2[t];
    }
}

// ---------------- GEMM1 (f32x2 packed) + fused att1 dots ----------------
__global__ void k_gemm1t(const float* __restrict__ X, const float* __restrict__ W,
                         const float* __restrict__ a1s, const float* __restrict__ a1d) {
    __shared__ float xsT[128 * 36];          // [k][row], pad 36
    int tid = threadIdx.x;
    int rowbase = blockIdx.x * 32;
    #pragma unroll 4
    for (int r = 0; r < 32; r++)
        xsT[tid * 36 + r] = X[(size_t)(rowbase + r) * 128 + tid];
    __syncthreads();
    unsigned long long acc2[16];
    #pragma unroll
    for (int p = 0; p < 16; p++) acc2[p] = 0ull;
    for (int k = 0; k < 128; k++) {
        float wk = W[k * 128 + tid];
        unsigned long long wk2 = pack2(wk, wk);
        const double2* xp = (const double2*)&xsT[k * 36];
        #pragma unroll
        for (int rr = 0; rr < 4; rr++) {
            double2 xv = xp[rr];
            ffma2(acc2[rr*4+0], __double_as_longlong(xv.x), wk2);
            ffma2(acc2[rr*4+1], __double_as_longlong(xv.y), wk2);
            double2 xw = xp[rr + 4];
            ffma2(acc2[rr*4+2], __double_as_longlong(xw.x), wk2);
            ffma2(acc2[rr*4+3], __double_as_longlong(xw.y), wk2);
        }
    }
    float as = a1s[tid], ad = a1d[tid];
    int lane = tid & 31, h = tid >> 5;
    #pragma unroll
    for (int rr = 0; rr < 4; rr++) {
        #pragma unroll
        for (int q = 0; q < 4; q++) {
            int r0 = (q >> 1) * 16 + rr * 4 + (q & 1) * 2;
            float lo, hi; unpack2(acc2[rr*4+q], lo, hi);
            g_h1[(size_t)(rowbase + r0) * 128 + tid] = lo;
            g_h1[(size_t)(rowbase + r0 + 1) * 128 + tid] = hi;
            float sl = lo * as, dl = lo * ad, sh = hi * as, dh = hi * ad;
            #pragma unroll
            for (int o = 16; o; o >>= 1) {
                sl += __shfl_xor_sync(~0u, sl, o);
                dl += __shfl_xor_sync(~0u, dl, o);
                sh += __shfl_xor_sync(~0u, sh, o);
                dh += __shfl_xor_sync(~0u, dh, o);
            }
            if (lane == 0) {
                g_als1[(rowbase + r0) * 4 + h] = sl;
                g_ald1[(rowbase + r0) * 4 + h] = dl;
                g_als1[(rowbase + r0 + 1) * 4 + h] = sh;
                g_ald1[(rowbase + r0 + 1) * 4 + h] = dh;
            }
        }
    }
}

// ---------------- layer-1 fused aggregation: warp per node ----------------
// A: self-loop score = mean of edge scores (register-resident after reduce)
// B: p = exp(lrelu(logit)), z-reduce      C: serial gather, scale by 1/z at end
__global__ void k_agg1f(const float* __restrict__ b1) {
    int wid = (blockIdx.x * blockDim.x + threadIdx.x) >> 5;
    int lane = threadIdx.x & 31;
    if (wid >= NN) return;
    int st = g_offsets[wid], en = g_offsets[wid + 1];
    // pass A
    float s0 = 0.f, s1 = 0.f, s2 = 0.f, s3 = 0.f;
    int selfpos = -1;
    for (int i = st + lane; i < en; i += 32) {
        if (g_ceid[i] < EE) {
            float4 a = g_cal1[i];
            s0 += a.x; s1 += a.y; s2 += a.z; s3 += a.w;
        } else selfpos = i;
    }
    #pragma unroll
    for (int o = 16; o; o >>= 1) {
        s0 += __shfl_xor_sync(~0u, s0, o);
        s1 += __shfl_xor_sync(~0u, s1, o);
        s2 += __shfl_xor_sync(~0u, s2, o);
        s3 += __shfl_xor_sync(~0u, s3, o);
        selfpos = max(selfpos, __shfl_xor_sync(~0u, selfpos, o));
    }
    float inv = 1.f / fmaxf((float)(en - st - 1), 1.f);
    float4 selfsc = make_float4(s0 * inv, s1 * inv, s2 * inv, s3 * inv);
    // pass B
    float4 ald = *(const float4*)&g_ald1[wid * 4];
    float z0 = 0.f, z1 = 0.f, z2 = 0.f, z3 = 0.f;
    for (int i = st + lane; i < en; i += 32) {
        int s = g_csrc[i];
        float4 als = *(const float4*)&g_als1[s * 4];
        float4 ae = (i == selfpos) ? selfsc : g_cal1[i];
        float p0 = __expf(lrelu(als.x + ald.x + ae.x));
        float p1 = __expf(lrelu(als.y + ald.y + ae.y));
        float p2 = __expf(lrelu(als.z + ald.z + ae.z));
        float p3 = __expf(lrelu(als.w + ald.w + ae.w));
        g_alpha1[i] = make_float4(p0, p1, p2, p3);
        z0 += p0; z1 += p1; z2 += p2; z3 += p3;
    }
    #pragma unroll
    for (int o = 16; o; o >>= 1) {
        z0 += __shfl_xor_sync(~0u, z0, o);
        z1 += __shfl_xor_sync(~0u, z1, o);
        z2 += __shfl_xor_sync(~0u, z2, o);
        z3 += __shfl_xor_sync(~0u, z3, o);
    }
    int h = lane >> 3;
    float zh = (h == 0) ? z0 : (h == 1) ? z1 : (h == 2) ? z2 : z3;
    float invz = 1.f / zh;
    // pass C
    float4 acc = make_float4(0.f, 0.f, 0.f, 0.f);
    for (int i = st; i < en; i++) {
        int s = g_csrc[i];
        float a = ((const float*)&g_alpha1[i])[h];
        float4 hv = *(const float4*)&g_h1[(size_t)s * 128 + lane * 4];
        acc.x += a * hv.x; acc.y += a * hv.y;
        acc.z += a * hv.z; acc.w += a * hv.w;
    }
    int j = lane * 4;
    float4 o;
    o.x = elu(acc.x * invz + b1[j+0]); o.y = elu(acc.y * invz + b1[j+1]);
    o.z = elu(acc.z * invz + b1[j+2]); o.w = elu(acc.w * invz + b1[j+3]);
    *(float4*)&g_h1o[(size_t)wid * 128 + j] = o;
}

// ---------------- GEMM2 (f32x2 packed) + fused att2 dots ----------------
__global__ void k_gemm2t(const float* __restrict__ W2,
                         const float* __restrict__ a2s, const float* __restrict__ a2d) {
    __shared__ float xsT[128 * 36];
    int tid = threadIdx.x;
    int c = tid & 31, g = tid >> 5;
    int rowbase = blockIdx.x * 32;
    for (int i = tid; i < 32 * 128; i += 128) {
        int r = i >> 7, k = i & 127;
        xsT[k * 36 + r] = g_h1o[(size_t)(rowbase + r) * 128 + k];
    }
    __syncthreads();
    unsigned long long acc2[4];
    #pragma unroll
    for (int p = 0; p < 4; p++) acc2[p] = 0ull;
    for (int k = 0; k < 128; k++) {
        float wk = W2[k * 32 + c];
        unsigned long long wk2 = pack2(wk, wk);
        const double2* xp = (const double2*)&xsT[k * 36 + g * 8];
        double2 x0 = xp[0], x1 = xp[1];
        ffma2(acc2[0], __double_as_longlong(x0.x), wk2);
        ffma2(acc2[1], __double_as_longlong(x0.y), wk2);
        ffma2(acc2[2], __double_as_longlong(x1.x), wk2);
        ffma2(acc2[3], __double_as_longlong(x1.y), wk2);
    }
    float as = a2s[c], ad = a2d[c];
    #pragma unroll
    for (int p = 0; p < 4; p++) {
        float lo, hi; unpack2(acc2[p], lo, hi);
        int r0 = rowbase + g * 8 + p * 2;
        g_h2l[(size_t)r0 * 32 + c] = lo;
        g_h2l[(size_t)(r0 + 1) * 32 + c] = hi;
        float sl = lo * as, dl = lo * ad, sh = hi * as, dh = hi * ad;
        #pragma unroll
        for (int o = 16; o; o >>= 1) {
            sl += __shfl_xor_sync(~0u, sl, o);
            dl += __shfl_xor_sync(~0u, dl, o);
            sh += __shfl_xor_sync(~0u, sh, o);
            dh += __shfl_xor_sync(~0u, dh, o);
        }
        if (c == 0) {
            g_als2[r0] = sl; g_ald2[r0] = dl;
            g_als2[r0 + 1] = sh; g_ald2[r0 + 1] = dh;
        }
    }
}

// ---------------- layer-2 fused aggregation: warp per node (+ alpha output) ----------------
__global__ void k_agg2f(const float* __restrict__ b2, float* __restrict__ outH2,
                        float* __restrict__ outAlpha) {
    int wid = (blockIdx.x * blockDim.x + threadIdx.x) >> 5;
    int lane = threadIdx.x & 31;
    if (wid >= NN) return;
    int st = g_offsets[wid], en = g_offsets[wid + 1];
    // pass A
    float u = 0.f;
    int selfpos = -1;
    for (int i = st + lane; i < en; i += 32) {
        if (g_ceid[i] < EE) u += g_cal2[i];
        else selfpos = i;
    }
    #pragma unroll
    for (int o = 16; o; o >>= 1) {
        u += __shfl_xor_sync(~0u, u, o);
        selfpos = max(selfpos, __shfl_xor_sync(~0u, selfpos, o));
    }
    float selfu = u / fmaxf((float)(en - st - 1), 1.f);
    // pass B
    float ald = g_ald2[wid];
    float z = 0.f;
    for (int i = st + lane; i < en; i += 32) {
        int s = g_csrc[i];
        float ae = (i == selfpos) ? selfu : g_cal2[i];
        float p = __expf(lrelu(g_als2[s] + ald + ae));
        g_alpha2[i] = p;
        z += p;
    }
    #pragma unroll
    for (int o = 16; o; o >>= 1) z += __shfl_xor_sync(~0u, z, o);
    float invz = 1.f / z;
    // pass C: serial gather
    float acc = 0.f;
    for (int i = st; i < en; i++) {
        int s = g_csrc[i];
        acc += g_alpha2[i] * g_h2l[(size_t)s * 32 + lane];
    }
    outH2[wid * 32 + lane] = elu(acc * invz + b2[lane]);
    // pass D: normalized alpha to output (by original edge id)
    if (outAlpha)
        for (int i = st + lane; i < en; i += 32)
            outAlpha[g_ceid[i]] = g_alpha2[i] * invz;
}

// ---------------- edge_index_sl output (as float) ----------------
__global__ void k_eidx(const int* __restrict__ ei, float* __restrict__ out) {
    int t = blockIdx.x * blockDim.x + threadIdx.x;
    if (t >= 2 * EP) return;
    int row = t / EP, j = t - row * EP;
    int v = (j < EE) ? ei[row * EE + j] : (j - EE);
    out[(size_t)NN * 32 + t] = (float)v;
}

// ---------------- launch ----------------
extern "C" void kernel_launch(void* const* d_in, const int* in_sizes, int n_in,
                              void* d_out, int out_size) {
    int ix, iei, iea, iW1, iW1e, ia1s, ia1d, ia1e, ib1, iW2, iW2e, ia2s, ia2d, ia2e, ib2;
    if (n_in >= 15 && in_sizes[0] == 16384) {
        iW1 = 0; iW1e = 1; iW2 = 2; iW2e = 3;
        ia1d = 4; ia1e = 5; ia1s = 6;
        ia2d = 7; ia2e = 8; ia2s = 9;
        ib1 = 10; ib2 = 11; iea = 12; iei = 13; ix = 14;
    } else {
        ix = 0; iei = 1; iea = 2; iW1 = 3; iW1e = 4;
        ia1s = 5; ia1d = 6; ia1e = 7; ib1 = 8;
        iW2 = 9; iW2e = 10; ia2s = 11; ia2d = 12; ia2e = 13; ib2 = 14;
    }
    const float* x   = (const float*)d_in[ix];
    const int*   ei  = (const int*)d_in[iei];
    const float* ea  = (const float*)d_in[iea];
    const float* W1  = (const float*)d_in[iW1];
    const float* a1s = (const float*)d_in[ia1s];
    const float* a1d = (const float*)d_in[ia1d];
    const float* b1  = (const float*)d_in[ib1];
    const float* W2  = (const float*)d_in[iW2];
    const float* a2s = (const float*)d_in[ia2s];
    const float* a2d = (const float*)d_in[ia2d];
    const float* b2  = (const float*)d_in[ib2];
    const float* W1e = (const float*)d_in[iW1e];
    const float* a1e = (const float*)d_in[ia1e];
    const float* W2e = (const float*)d_in[iW2e];
    const float* a2e = (const float*)d_in[ia2e];
    float* out = (float*)d_out;

    bool full = (out_size >= NN * 32 + 3 * EP);
    float* alphaOut = full ? out + (size_t)NN * 32 + 2 * (size_t)EP : nullptr;

    const int B = 256;
    kz<<<(NN + B - 1) / B, B>>>();
    k_prep<<<1, 128>>>(W1e, a1e, W2e, a2e);
    k_edge<<<EE / 512, 256>>>(ei, ea);                       // 2 edges/thread
    k_scan1<<<NBLK, 1024>>>();
    k_scan2<<<1, 1>>>();
    k_scan3<<<(NN + 1 + B - 1) / B, B>>>();
    k_scatter<<<(EP + B - 1) / B, B>>>(ei);
    k_gemm1t<<<NN / 32, 128>>>(x, W1, a1s, a1d);
    k_agg1f<<<(NN * 32 + B - 1) / B, B>>>(b1);               // warp per node, fused
    k_gemm2t<<<NN / 32, 128>>>(W2, a2s, a2d);
    k_agg2f<<<(NN * 32 + B - 1) / B, B>>>(b2, out, alphaOut);// warp per node, fused
    if (full) k_eidx<<<(2 * EP + B - 1) / B, B>>>(ei, out);
}